// round 5
// baseline (speedup 1.0000x reference)
#include <cuda_runtime.h>
#include <cstdint>

#define T_ 12
#define B_ 16
#define N_ 1024
#define H_ 64
#define L_ 2
#define PROJ_ 256
#define ROWS (T_*B_*N_)
#define HALF (ROWS/2)

// ---- scratch (device globals; allocation-free) ----
__device__ __align__(16) float g_seq [ROWS*2];
__device__ __align__(16) float g_p   [(size_t)ROWS*PROJ_];
__device__ __align__(16) float g_xp  [(size_t)ROWS*H_];
__device__ __align__(16) float g_h   [L_*2*N_*B_*H_];     // [l][d][n][b][64]
__device__ __align__(16) float g_xh  [2*N_*B_*128];       // [d][n][b][128]
__device__ __align__(16) float g_agg [2*N_*B_*128];
__device__ __align__(16) float g_zr  [2*N_*B_*128];
__device__ __align__(16) float g_xrh [2*N_*B_*128];
__device__ __align__(16) float g_v   [2*N_*B_*64];
__device__ __align__(16) float g_cl  [2*N_*B_*64];
__device__ __align__(16) float g_z   [2*N_*B_*64];
__device__ __align__(16) float g_wzr [L_*2*128*128];      // [l][d][f][col<64:Wz|>=64:Wr]
__device__ __align__(16) float g_wc  [L_*2*128*64];
__device__ __align__(16) float g_hcat[(size_t)L_*B_*N_*128];
__device__ __align__(16) float g_s1  [(size_t)L_*B_*N_*PROJ_];

// ---- threefry2x32-20, bit-exact JAX normal(key(42)) ----
__device__ __forceinline__ uint32_t rotl_(uint32_t x,int r){return (x<<r)|(x>>(32-r));}
__device__ float tf_noise(unsigned i)
{
    uint32_t x0,x1; bool second = (i >= (unsigned)HALF);
    if(second){x0=i-HALF; x1=i;} else {x0=i; x1=i+HALF;}
    const uint32_t ks0=0u, ks1=42u, ks2=0u^42u^0x1BD11BDAu;
    x0+=ks0; x1+=ks1;
#define TFR(r) {x0+=x1; x1=rotl_(x1,(r)); x1^=x0;}
    TFR(13)TFR(15)TFR(26)TFR(6)  x0+=ks1; x1+=ks2+1u;
    TFR(17)TFR(29)TFR(16)TFR(24) x0+=ks2; x1+=ks0+2u;
    TFR(13)TFR(15)TFR(26)TFR(6)  x0+=ks0; x1+=ks1+3u;
    TFR(17)TFR(29)TFR(16)TFR(24) x0+=ks1; x1+=ks2+4u;
    TFR(13)TFR(15)TFR(26)TFR(6)  x0+=ks2; x1+=ks0+5u;
#undef TFR
    uint32_t bits = second ? x1 : x0;
    float f = __uint_as_float((bits>>9)|0x3f800000u) - 1.0f;     // [0,1)
    const float lo = -0.99999994f;                                // nextafter(-1,0)
    float u = fmaxf(lo, fmaf(f, 2.0f, lo));                       // (1-lo) rounds to 2.0f
    return 1.41421356f * erfinvf(u) * 0.01f;
}

// ---- elementwise kernels ----
__global__ void seq_kernel(const float* __restrict__ in, const float* __restrict__ mk)
{
    unsigned i = blockIdx.x*256u + threadIdx.x;
    reinterpret_cast<float2*>(g_seq)[i] = make_float2(in[i] + tf_noise(i), mk[i]);
}

__global__ void pproj_kernel(const float* __restrict__ Wp1, const float* __restrict__ bp1)
{
    size_t gid = (size_t)blockIdx.x*256u + threadIdx.x;
    int j = (int)(gid & 255u); size_t row = gid >> 8;
    float2 s = reinterpret_cast<const float2*>(g_seq)[row];
    g_p[gid] = fmaxf(fmaf(s.x, Wp1[j], fmaf(s.y, Wp1[256+j], bp1[j])), 0.f);
}

__global__ void zero_h_kernel(){ g_h[blockIdx.x*256u + threadIdx.x] = 0.f; }

__global__ void pack_w_kernel(const float* Wz_f,const float* Wr_f,const float* Wc_f,
                              const float* Wz_r,const float* Wr_r,const float* Wc_r)
{
    unsigned idx = blockIdx.x*256u + threadIdx.x;
    if (idx < 65536u) {
        int col=idx&127, f=(idx>>7)&127, d=(idx>>14)&1, l=idx>>15;
        const float* Wz = d?Wz_r:Wz_f; const float* Wr = d?Wr_r:Wr_f;
        g_wzr[idx] = (col<64) ? Wz[(l*128+f)*64+col] : Wr[(l*128+f)*64+(col-64)];
    } else {
        unsigned k = idx - 65536u;
        int j=k&63, f=(k>>6)&127, d=(k>>13)&1, l=k>>14;
        g_wc[k] = (d?Wc_r:Wc_f)[(l*128+f)*64+j];
    }
}

// xh[d][n][b][0:64]=x, [64:128]=h
__global__ void build_xh_kernel(const float* __restrict__ x0, const float* __restrict__ x1,
                                int nstr, int bstr, const float* __restrict__ hbuf)
{
    unsigned idx = blockIdx.x*256u + threadIdx.x;     // 2^22
    int f=idx&127, b=(idx>>7)&15, n=(idx>>11)&1023, d=idx>>21;
    float v;
    if (f < 64) { const float* xb = d?x1:x0; v = xb[(size_t)n*nstr + (size_t)b*bstr + f]; }
    else        { v = hbuf[(((size_t)d*N_ + n)*B_ + b)*H_ + (f-64)]; }
    g_xh[idx] = v;
}

__global__ void zr_act_kernel(const float* __restrict__ x0, const float* __restrict__ x1,
                              int nstr, int bstr, const float* __restrict__ hbuf,
                              const float* bz0, const float* bz1,
                              const float* br0, const float* br1)
{
    unsigned idx = blockIdx.x*256u + threadIdx.x;     // 2^21
    int j=idx&63, b=(idx>>6)&15, n=(idx>>10)&1023, d=idx>>20;
    size_t zrb = ((size_t)(d*N_ + n))*2048 + (size_t)b*128;
    float zl = g_zr[zrb + j]      + (d?bz1:bz0)[j];
    float rl = g_zr[zrb + 64 + j] + (d?br1:br0)[j];
    float z = 1.f/(1.f + expf(-zl));
    float r = 1.f/(1.f + expf(-rl));
    size_t hofs = (((size_t)d*N_ + n)*B_ + b)*H_ + j;
    float h = hbuf[hofs];
    g_z[hofs] = z;
    const float* xb = d?x1:x0;
    float x = xb[(size_t)n*nstr + (size_t)b*bstr + j];
    size_t xrb = (((size_t)d*N_ + n)*B_ + b)*128;
    g_xrh[xrb + j]      = x;
    g_xrh[xrb + 64 + j] = r*h;
}

__global__ void update_kernel(float* __restrict__ hbuf, const float* bc0, const float* bc1)
{
    unsigned idx = blockIdx.x*256u + threadIdx.x;     // 2^21
    int j=idx&63, b=(idx>>6)&15, n=(idx>>10)&1023, d=idx>>20;
    float c = tanhf(g_cl[((size_t)(d*N_ + n))*1024 + (size_t)b*64 + j] + (d?bc1:bc0)[j]);
    size_t hofs = (((size_t)d*N_ + n)*B_ + b)*H_ + j;
    float z = g_z[hofs], h = hbuf[hofs];
    hbuf[hofs] = z*h + (1.f - z)*c;
}

// hcat[l][b][n][d*64+j]
__global__ void hcat_kernel()
{
    unsigned idx = blockIdx.x*256u + threadIdx.x;     // 2^22
    int jj=idx&127, n=(idx>>7)&1023, b=(idx>>17)&15, l=idx>>21;
    int d=jj>>6, h=jj&63;
    g_hcat[idx] = g_h[((((size_t)l*2 + d)*N_ + n)*B_ + b)*H_ + h];
}

// ---- register-tiled SGEMM: C[M,N]=A[M,K]@B[K,N], BM=128, BK=8, 256 thr ----
template<int BN, bool RELU, bool BIAS>
__global__ __launch_bounds__(256)
void sgemm_k(const float* __restrict__ A, const float* __restrict__ Bm,
             float* __restrict__ C, int M, int N, int K,
             size_t sAz, size_t sBz, size_t sCz, const float* __restrict__ bias)
{
    constexpr int TN = BN/16;
    __shared__ float As[8][128];
    __shared__ float Bs[8][BN];
    const int tid=threadIdx.x, tx=tid&15, ty=tid>>4;
    const int m0=blockIdx.y*128, n0=blockIdx.x*BN;
    A += (size_t)blockIdx.z*sAz; Bm += (size_t)blockIdx.z*sBz; C += (size_t)blockIdx.z*sCz;

    float acc[8][TN];
    #pragma unroll
    for(int i=0;i<8;i++)
    {
        #pragma unroll
        for(int j=0;j<TN;j++) acc[i][j]=0.f;
    }

    const int arow=tid>>1, ak=(tid&1)*4, br=tid>>5;
    for(int kt=0; kt<K; kt+=8){
        float4 av = *reinterpret_cast<const float4*>(A + (size_t)(m0+arow)*K + kt + ak);
        As[ak+0][arow]=av.x; As[ak+1][arow]=av.y; As[ak+2][arow]=av.z; As[ak+3][arow]=av.w;
        if (BN==128){
            int bc=(tid&31)*4;
            float4 bv = *reinterpret_cast<const float4*>(Bm + (size_t)(kt+br)*N + n0 + bc);
            *reinterpret_cast<float4*>(&Bs[br][bc]) = bv;
        } else {
            int bc=(tid&31)*2;
            float2 bv = *reinterpret_cast<const float2*>(Bm + (size_t)(kt+br)*N + n0 + bc);
            *reinterpret_cast<float2*>(&Bs[br][bc]) = bv;
        }
        __syncthreads();
        #pragma unroll
        for(int k=0;k<8;k++){
            float4 a0 = *reinterpret_cast<const float4*>(&As[k][ty*8]);
            float4 a1 = *reinterpret_cast<const float4*>(&As[k][ty*8+4]);
            float av8[8]={a0.x,a0.y,a0.z,a0.w,a1.x,a1.y,a1.z,a1.w};
            float bv[TN];
            #pragma unroll
            for(int j=0;j<TN;j+=4){
                float4 b4 = *reinterpret_cast<const float4*>(&Bs[k][tx*TN+j]);
                bv[j]=b4.x; bv[j+1]=b4.y; bv[j+2]=b4.z; bv[j+3]=b4.w;
            }
            #pragma unroll
            for(int i=0;i<8;i++)
            {
                #pragma unroll
                for(int j=0;j<TN;j++) acc[i][j]=fmaf(av8[i],bv[j],acc[i][j]);
            }
        }
        __syncthreads();
    }
    #pragma unroll
    for(int i=0;i<8;i++){
        size_t cro = (size_t)(m0+ty*8+i)*N + n0 + tx*TN;
        #pragma unroll
        for(int j=0;j<TN;j+=4){
            float4 v = make_float4(acc[i][j],acc[i][j+1],acc[i][j+2],acc[i][j+3]);
            if (BIAS){ v.x+=bias[n0+tx*TN+j]; v.y+=bias[n0+tx*TN+j+1];
                       v.z+=bias[n0+tx*TN+j+2]; v.w+=bias[n0+tx*TN+j+3]; }
            if (RELU){ v.x=fmaxf(v.x,0.f); v.y=fmaxf(v.y,0.f); v.z=fmaxf(v.z,0.f); v.w=fmaxf(v.w,0.f); }
            *reinterpret_cast<float4*>(&C[cro+j]) = v;
        }
    }
}

// ---- host ----
extern "C" void kernel_launch(void* const* d_in, const int* in_sizes, int n_in,
                              void* d_out, int out_size)
{
    const float *inp =(const float*)d_in[0], *msk =(const float*)d_in[1];
    const float *adj =(const float*)d_in[2];
    const float *Wp1 =(const float*)d_in[3], *bp1=(const float*)d_in[4];
    const float *Wp2 =(const float*)d_in[5], *bp2=(const float*)d_in[6];
    const float *Wz_f=(const float*)d_in[7], *Wr_f=(const float*)d_in[8], *Wc_f=(const float*)d_in[9];
    const float *bz_f=(const float*)d_in[10],*br_f=(const float*)d_in[11],*bc_f=(const float*)d_in[12];
    const float *Wz_r=(const float*)d_in[13],*Wr_r=(const float*)d_in[14],*Wc_r=(const float*)d_in[15];
    const float *bz_r=(const float*)d_in[16],*br_r=(const float*)d_in[17],*bc_r=(const float*)d_in[18];
    const float *Wd1 =(const float*)d_in[19],*bd1=(const float*)d_in[20];
    const float *Wd2 =(const float*)d_in[21],*bd2=(const float*)d_in[22];
    float* outp = (float*)d_out;

    void* vp;
    #define GS(nm) cudaGetSymbolAddress(&vp,nm); float* p_##nm=(float*)vp;
    GS(g_p) GS(g_xp) GS(g_h) GS(g_xh) GS(g_agg) GS(g_zr) GS(g_xrh)
    GS(g_v) GS(g_cl) GS(g_wzr) GS(g_wc) GS(g_hcat) GS(g_s1)
    #undef GS

    seq_kernel  <<<ROWS/256,256>>>(inp, msk);
    pproj_kernel<<<ROWS,256>>>(Wp1, bp1);
    sgemm_k<64,false,true><<<dim3(1,ROWS/128,1),256>>>(p_g_p, Wp2, p_g_xp, ROWS,64,256, 0,0,0, bp2);
    zero_h_kernel<<<(L_*2*N_*B_*H_)/256,256>>>();
    pack_w_kernel<<<384,256>>>(Wz_f,Wr_f,Wc_f,Wz_r,Wr_r,Wc_r);

    for (int t=0; t<T_; t++){
        for (int l=0; l<L_; l++){
            const float *x0,*x1; int nstr,bstr;
            if (l==0){ x0 = p_g_xp + (size_t)t*B_*N_*H_;
                       x1 = p_g_xp + (size_t)(T_-1-t)*B_*N_*H_;
                       nstr = H_; bstr = N_*H_; }
            else     { x0 = p_g_h; x1 = p_g_h + N_*B_*H_;
                       nstr = B_*H_; bstr = H_; }
            float* hbuf = p_g_h + (size_t)l*2*N_*B_*H_;

            build_xh_kernel<<<16384,256>>>(x0,x1,nstr,bstr,hbuf);
            sgemm_k<128,false,false><<<dim3(16,8,2),256>>>(
                adj, p_g_xh, p_g_agg, 1024,2048,1024,
                0, (size_t)N_*2048, (size_t)N_*2048, nullptr);
            sgemm_k<128,false,false><<<dim3(1,128,2),256>>>(
                p_g_agg, p_g_wzr + l*32768, p_g_zr, 16384,128,128,
                (size_t)1<<21, 16384, (size_t)1<<21, nullptr);
            zr_act_kernel<<<8192,256>>>(x0,x1,nstr,bstr,hbuf,
                bz_f+l*64, bz_r+l*64, br_f+l*64, br_r+l*64);
            sgemm_k<64,false,false><<<dim3(1,128,2),256>>>(
                p_g_xrh, p_g_wc + l*16384, p_g_v, 16384,64,128,
                (size_t)1<<21, 8192, (size_t)1<<20, nullptr);
            sgemm_k<128,false,false><<<dim3(8,8,2),256>>>(
                adj, p_g_v, p_g_cl, 1024,1024,1024,
                0, (size_t)1<<20, (size_t)1<<20, nullptr);
            update_kernel<<<8192,256>>>(hbuf, bc_f+l*64, bc_r+l*64);
        }
    }

    hcat_kernel<<<16384,256>>>();
    sgemm_k<128,true ,true><<<dim3(2,256,1),256>>>(p_g_hcat, Wd1, p_g_s1, 32768,256,128, 0,0,0, bd1);
    sgemm_k<64 ,false,true><<<dim3(1,256,1),256>>>(p_g_s1,  Wd2, outp,  32768,64,256,  0,0,0, bd2);
}

// round 7
// speedup vs baseline: 2.0928x; 2.0928x over previous
#include <cuda_runtime.h>
#include <cuda_bf16.h>
#include <cstdint>

#define T_ 12
#define B_ 16
#define N_ 1024
#define H_ 64
#define L_ 2
#define PROJ_ 256
#define ROWS (T_*B_*N_)
#define HALF (ROWS/2)

// ---- scratch (device globals; allocation-free) ----
__device__ __align__(16) float g_seq [ROWS*2];
__device__ __align__(16) float g_p   [(size_t)ROWS*PROJ_];
__device__ __align__(16) float g_xp  [(size_t)ROWS*H_];
__device__ __align__(16) float g_h   [L_*2*N_*B_*H_];     // [l][d][n][b][64]
__device__ __align__(16) float g_xh  [2*N_*B_*128];       // [d][n][2048]
__device__ __align__(16) float g_agg [2*N_*B_*128];
__device__ __align__(16) float g_zr  [2*N_*B_*128];
__device__ __align__(16) float g_xrh [2*N_*B_*128];
__device__ __align__(16) float g_v   [2*N_*B_*64];        // [d][n][1024]
__device__ __align__(16) float g_cl  [2*N_*B_*64];
__device__ __align__(16) float g_z   [2*N_*B_*64];
__device__ __align__(16) float g_wzr [L_*2*128*128];
__device__ __align__(16) float g_wc  [L_*2*128*64];
__device__ __align__(16) float g_hcat[(size_t)L_*B_*N_*128];
__device__ __align__(16) float g_s1  [(size_t)L_*B_*N_*PROJ_];
// bf16-split operands for tensor-core GEMM
__device__ __align__(256) __nv_bfloat16 g_adj_hi[1024*1024];
__device__ __align__(256) __nv_bfloat16 g_adj_lo[1024*1024];
__device__ __align__(256) __nv_bfloat16 g_bt_hi[(size_t)4096*1024];
__device__ __align__(256) __nv_bfloat16 g_bt_lo[(size_t)4096*1024];

// ---- threefry2x32-20, bit-exact JAX normal(key(42)) ----
__device__ __forceinline__ uint32_t rotl_(uint32_t x,int r){return (x<<r)|(x>>(32-r));}
__device__ float tf_noise(unsigned i)
{
    uint32_t x0,x1; bool second = (i >= (unsigned)HALF);
    if(second){x0=i-HALF; x1=i;} else {x0=i; x1=i+HALF;}
    const uint32_t ks0=0u, ks1=42u, ks2=0u^42u^0x1BD11BDAu;
    x0+=ks0; x1+=ks1;
#define TFR(r) {x0+=x1; x1=rotl_(x1,(r)); x1^=x0;}
    TFR(13)TFR(15)TFR(26)TFR(6)  x0+=ks1; x1+=ks2+1u;
    TFR(17)TFR(29)TFR(16)TFR(24) x0+=ks2; x1+=ks0+2u;
    TFR(13)TFR(15)TFR(26)TFR(6)  x0+=ks0; x1+=ks1+3u;
    TFR(17)TFR(29)TFR(16)TFR(24) x0+=ks1; x1+=ks2+4u;
    TFR(13)TFR(15)TFR(26)TFR(6)  x0+=ks2; x1+=ks0+5u;
#undef TFR
    uint32_t bits = second ? x1 : x0;
    float f = __uint_as_float((bits>>9)|0x3f800000u) - 1.0f;
    const float lo = -0.99999994f;
    float u = fmaxf(lo, fmaf(f, 2.0f, lo));
    return 1.41421356f * erfinvf(u) * 0.01f;
}

// ---- elementwise kernels (validated in R5 run) ----
__global__ void seq_kernel(const float* __restrict__ in, const float* __restrict__ mk)
{
    unsigned i = blockIdx.x*256u + threadIdx.x;
    reinterpret_cast<float2*>(g_seq)[i] = make_float2(in[i] + tf_noise(i), mk[i]);
}

__global__ void pproj_kernel(const float* __restrict__ Wp1, const float* __restrict__ bp1)
{
    size_t gid = (size_t)blockIdx.x*256u + threadIdx.x;
    int j = (int)(gid & 255u); size_t row = gid >> 8;
    float2 s = reinterpret_cast<const float2*>(g_seq)[row];
    g_p[gid] = fmaxf(fmaf(s.x, Wp1[j], fmaf(s.y, Wp1[256+j], bp1[j])), 0.f);
}

__global__ void zero_h_kernel(){ g_h[blockIdx.x*256u + threadIdx.x] = 0.f; }

__global__ void pack_w_kernel(const float* Wz_f,const float* Wr_f,const float* Wc_f,
                              const float* Wz_r,const float* Wr_r,const float* Wc_r)
{
    unsigned idx = blockIdx.x*256u + threadIdx.x;
    if (idx < 65536u) {
        int col=idx&127, f=(idx>>7)&127, d=(idx>>14)&1, l=idx>>15;
        const float* Wz = d?Wz_r:Wz_f; const float* Wr = d?Wr_r:Wr_f;
        g_wzr[idx] = (col<64) ? Wz[(l*128+f)*64+col] : Wr[(l*128+f)*64+(col-64)];
    } else {
        unsigned k = idx - 65536u;
        int j=k&63, f=(k>>6)&127, d=(k>>13)&1, l=k>>14;
        g_wc[k] = (d?Wc_r:Wc_f)[(l*128+f)*64+j];
    }
}

__global__ void build_xh_kernel(const float* __restrict__ x0, const float* __restrict__ x1,
                                int nstr, int bstr, const float* __restrict__ hbuf)
{
    unsigned idx = blockIdx.x*256u + threadIdx.x;
    int f=idx&127, b=(idx>>7)&15, n=(idx>>11)&1023, d=idx>>21;
    float v;
    if (f < 64) { const float* xb = d?x1:x0; v = xb[(size_t)n*nstr + (size_t)b*bstr + f]; }
    else        { v = hbuf[(((size_t)d*N_ + n)*B_ + b)*H_ + (f-64)]; }
    g_xh[idx] = v;
}

__global__ void zr_act_kernel(const float* __restrict__ x0, const float* __restrict__ x1,
                              int nstr, int bstr, const float* __restrict__ hbuf,
                              const float* bz0, const float* bz1,
                              const float* br0, const float* br1)
{
    unsigned idx = blockIdx.x*256u + threadIdx.x;
    int j=idx&63, b=(idx>>6)&15, n=(idx>>10)&1023, d=idx>>20;
    size_t zrb = ((size_t)(d*N_ + n))*2048 + (size_t)b*128;
    float zl = g_zr[zrb + j]      + (d?bz1:bz0)[j];
    float rl = g_zr[zrb + 64 + j] + (d?br1:br0)[j];
    float z = 1.f/(1.f + expf(-zl));
    float r = 1.f/(1.f + expf(-rl));
    size_t hofs = (((size_t)d*N_ + n)*B_ + b)*H_ + j;
    float h = hbuf[hofs];
    g_z[hofs] = z;
    const float* xb = d?x1:x0;
    float x = xb[(size_t)n*nstr + (size_t)b*bstr + j];
    size_t xrb = (((size_t)d*N_ + n)*B_ + b)*128;
    g_xrh[xrb + j]      = x;
    g_xrh[xrb + 64 + j] = r*h;
}

__global__ void update_kernel(float* __restrict__ hbuf, const float* bc0, const float* bc1)
{
    unsigned idx = blockIdx.x*256u + threadIdx.x;
    int j=idx&63, b=(idx>>6)&15, n=(idx>>10)&1023, d=idx>>20;
    float c = tanhf(g_cl[((size_t)(d*N_ + n))*1024 + (size_t)b*64 + j] + (d?bc1:bc0)[j]);
    size_t hofs = (((size_t)d*N_ + n)*B_ + b)*H_ + j;
    float z = g_z[hofs], h = hbuf[hofs];
    hbuf[hofs] = z*h + (1.f - z)*c;
}

__global__ void hcat_kernel()
{
    unsigned idx = blockIdx.x*256u + threadIdx.x;
    int jj=idx&127, n=(idx>>7)&1023, b=(idx>>17)&15, l=idx>>21;
    int d=jj>>6, h=jj&63;
    g_hcat[idx] = g_h[((((size_t)l*2 + d)*N_ + n)*B_ + b)*H_ + h];
}

// ---- bf16 split helpers ----
__global__ void adjsplit_kernel(const float* __restrict__ adj)
{
    unsigned i = blockIdx.x*256u + threadIdx.x;
    float a = adj[i];
    __nv_bfloat16 h = __float2bfloat16_rn(a);
    g_adj_hi[i] = h;
    g_adj_lo[i] = __float2bfloat16_rn(a - __bfloat162float(h));
}

// transpose + split: src[(d*1024+n)*C + c] -> bt[(d*C+c)*1024 + n]
__global__ void tsplit_kernel(const float* __restrict__ src, int C)
{
    __shared__ float tile[32][33];
    int d = blockIdx.z;
    int c0 = blockIdx.x*32, n0 = blockIdx.y*32;
    int tx = threadIdx.x & 31, ty = threadIdx.x >> 5;
    const float* s = src + ((size_t)(d*1024 + n0))*C + c0;
    #pragma unroll
    for (int i=0;i<4;i++)
        tile[ty+8*i][tx] = s[(size_t)(ty+8*i)*C + tx];
    __syncthreads();
    size_t ob = ((size_t)(d*C + c0))*1024 + n0;
    #pragma unroll
    for (int i=0;i<4;i++){
        int c = ty + 8*i;
        float v = tile[tx][c];
        __nv_bfloat16 h = __float2bfloat16_rn(v);
        g_bt_hi[ob + (size_t)c*1024 + tx] = h;
        g_bt_lo[ob + (size_t)c*1024 + tx] = __float2bfloat16_rn(v - __bfloat162float(h));
    }
}

// ---- legacy-tensor-core split-bf16 GEMM (mma.sync + ldmatrix + cp.async) ----
__device__ __forceinline__ uint32_t smem_u32_(const void* p){
    uint32_t a;
    asm("{ .reg .u64 t; cvta.to.shared.u64 t, %1; cvt.u32.u64 %0, t; }":"=r"(a):"l"(p));
    return a;
}
#define LDSM_X4(r0,r1,r2,r3,addr) \
    asm volatile("ldmatrix.sync.aligned.m8n8.x4.shared.b16 {%0,%1,%2,%3}, [%4];" \
        : "=r"(r0),"=r"(r1),"=r"(r2),"=r"(r3) : "r"(addr))
#define MMA16816(d0,d1,d2,d3,a0,a1,a2,a3,b0,b1) \
    asm volatile("mma.sync.aligned.m16n8k16.row.col.f32.bf16.bf16.f32 " \
        "{%0,%1,%2,%3}, {%4,%5,%6,%7}, {%8,%9}, {%0,%1,%2,%3};" \
        : "+f"(d0),"+f"(d1),"+f"(d2),"+f"(d3) \
        : "r"(a0),"r"(a1),"r"(a2),"r"(a3),"r"(b0),"r"(b1))
#define CP16(dst,src) asm volatile("cp.async.cg.shared.global [%0], [%1], 16;"::"r"(dst),"l"(src))

#define TC_DYNSMEM 65536   // 2 stages x (A 16KB + B 16KB)

__device__ __forceinline__ void tc_load_stage(
    int it, uint32_t sbuf,
    const __nv_bfloat16* __restrict__ Ahi, const __nv_bfloat16* __restrict__ Alo,
    const __nv_bfloat16* __restrict__ Bhi, const __nv_bfloat16* __restrict__ Blo,
    int m0, int n0, int tid)
{
    int p = it >> 4, kc = it & 15;
    int koff = kc*64;
    const __nv_bfloat16* Ag = (p==2) ? Alo : Ahi;
    const __nv_bfloat16* Bg = (p==1) ? Blo : Bhi;
    #pragma unroll
    for (int i=0;i<4;i++){
        int idx = tid + 256*i;          // 0..1023 (128 rows x 8 segs)
        int row = idx >> 3, seg = idx & 7;
        uint32_t sw = (uint32_t)((seg ^ (row & 7)) << 4);
        uint32_t da = sbuf + (uint32_t)(row*128) + sw;
        CP16(da, (const void*)(Ag + (size_t)(m0+row)*1024 + koff + seg*8));
        uint32_t db = sbuf + 16384u + (uint32_t)(row*128) + sw;
        CP16(db, (const void*)(Bg + (size_t)(n0+row)*1024 + koff + seg*8));
    }
    asm volatile("cp.async.commit_group;");
}

// C[1024 rows, 2*Wd cols] = adj @ X ; A split (hi/lo) [1024x1024], B transposed split [cols x 1024]
__global__ __launch_bounds__(256,1)
void tc_gemm(const __nv_bfloat16* __restrict__ Ahi, const __nv_bfloat16* __restrict__ Alo,
             const __nv_bfloat16* __restrict__ Bhi, const __nv_bfloat16* __restrict__ Blo,
             float* __restrict__ Cout, int Wd)
{
    extern __shared__ __align__(128) char dyn_[];
    uint32_t sbase = smem_u32_(dyn_);
    const int tid = threadIdx.x, wid = tid>>5, lane = tid&31;
    const int mw = (wid>>2)*64, nw = (wid&3)*32;
    const int m0 = blockIdx.y*128, n0 = blockIdx.x*128;

    float acc[4][4][4];
    #pragma unroll
    for (int i=0;i<4;i++)
        #pragma unroll
        for (int j=0;j<4;j++)
            #pragma unroll
            for (int q=0;q<4;q++) acc[i][j][q]=0.f;

    tc_load_stage(0, sbase, Ahi,Alo,Bhi,Blo, m0,n0, tid);

    for (int it=0; it<48; it++){
        uint32_t buf = (uint32_t)(it & 1);
        if (it+1 < 48){
            tc_load_stage(it+1, sbase + (buf^1u)*32768u, Ahi,Alo,Bhi,Blo, m0,n0, tid);
            asm volatile("cp.async.wait_group 1;");
        } else {
            asm volatile("cp.async.wait_group 0;");
        }
        __syncthreads();

        uint32_t sA = sbase + buf*32768u;
        uint32_t sB = sA + 16384u;
        #pragma unroll
        for (int ks=0; ks<4; ks++){
            uint32_t aF[4][4], bF[2][4];
            #pragma unroll
            for (int tm=0;tm<4;tm++){
                int row = mw + tm*16 + ((lane>>3)&1)*8 + (lane&7);
                int ksg = ks*2 + (lane>>4);
                uint32_t ad = sA + (uint32_t)(row*128) + (uint32_t)(((ksg ^ (row&7)))<<4);
                LDSM_X4(aF[tm][0],aF[tm][1],aF[tm][2],aF[tm][3], ad);
            }
            #pragma unroll
            for (int np=0;np<2;np++){
                int row = nw + np*16 + ((lane>>4)&1)*8 + (lane&7);
                int ksg = ks*2 + ((lane>>3)&1);
                uint32_t ad = sB + (uint32_t)(row*128) + (uint32_t)(((ksg ^ (row&7)))<<4);
                LDSM_X4(bF[np][0],bF[np][1],bF[np][2],bF[np][3], ad);
            }
            #pragma unroll
            for (int tm=0;tm<4;tm++)
            {
                #pragma unroll
                for (int tn=0;tn<4;tn++){
                    uint32_t b0 = bF[tn>>1][(tn&1)?2:0];
                    uint32_t b1 = bF[tn>>1][(tn&1)?3:1];
                    MMA16816(acc[tm][tn][0],acc[tm][tn][1],acc[tm][tn][2],acc[tm][tn][3],
                             aF[tm][0],aF[tm][1],aF[tm][2],aF[tm][3], b0,b1);
                }
            }
        }
        __syncthreads();
    }

    // epilogue: c0,c1 -> (m, n/n+1); c2,c3 -> (m+8, n/n+1)
    const int d = n0 / Wd;
    #pragma unroll
    for (int tm=0;tm<4;tm++)
    {
        #pragma unroll
        for (int tn=0;tn<4;tn++){
            int m = m0 + mw + tm*16 + (lane>>2);
            int nc = (n0 % Wd) + nw + tn*8 + (lane&3)*2;
            float* o0 = Cout + ((size_t)(d*1024 + m))*(size_t)Wd + nc;
            *reinterpret_cast<float2*>(o0) = make_float2(acc[tm][tn][0], acc[tm][tn][1]);
            float* o1 = o0 + (size_t)8*(size_t)Wd;
            *reinterpret_cast<float2*>(o1) = make_float2(acc[tm][tn][2], acc[tm][tn][3]);
        }
    }
}

// ---- register-tiled fp32 SGEMM (validated) ----
template<int BN, bool RELU, bool BIAS>
__global__ __launch_bounds__(256)
void sgemm_k(const float* __restrict__ A, const float* __restrict__ Bm,
             float* __restrict__ C, int M, int N, int K,
             size_t sAz, size_t sBz, size_t sCz, const float* __restrict__ bias)
{
    constexpr int TN = BN/16;
    __shared__ float As[8][128];
    __shared__ float Bs[8][BN];
    const int tid=threadIdx.x, tx=tid&15, ty=tid>>4;
    const int m0=blockIdx.y*128, n0=blockIdx.x*BN;
    A += (size_t)blockIdx.z*sAz; Bm += (size_t)blockIdx.z*sBz; C += (size_t)blockIdx.z*sCz;

    float acc[8][TN];
    #pragma unroll
    for(int i=0;i<8;i++)
    {
        #pragma unroll
        for(int j=0;j<TN;j++) acc[i][j]=0.f;
    }

    const int arow=tid>>1, ak=(tid&1)*4, br=tid>>5;
    for(int kt=0; kt<K; kt+=8){
        float4 av = *reinterpret_cast<const float4*>(A + (size_t)(m0+arow)*K + kt + ak);
        As[ak+0][arow]=av.x; As[ak+1][arow]=av.y; As[ak+2][arow]=av.z; As[ak+3][arow]=av.w;
        if (BN==128){
            int bc=(tid&31)*4;
            float4 bv = *reinterpret_cast<const float4*>(Bm + (size_t)(kt+br)*N + n0 + bc);
            *reinterpret_cast<float4*>(&Bs[br][bc]) = bv;
        } else {
            int bc=(tid&31)*2;
            float2 bv = *reinterpret_cast<const float2*>(Bm + (size_t)(kt+br)*N + n0 + bc);
            *reinterpret_cast<float2*>(&Bs[br][bc]) = bv;
        }
        __syncthreads();
        #pragma unroll
        for(int k=0;k<8;k++){
            float4 a0 = *reinterpret_cast<const float4*>(&As[k][ty*8]);
            float4 a1 = *reinterpret_cast<const float4*>(&As[k][ty*8+4]);
            float av8[8]={a0.x,a0.y,a0.z,a0.w,a1.x,a1.y,a1.z,a1.w};
            float bv[TN];
            #pragma unroll
            for(int j=0;j<TN;j+=4){
                float4 b4 = *reinterpret_cast<const float4*>(&Bs[k][tx*TN+j]);
                bv[j]=b4.x; bv[j+1]=b4.y; bv[j+2]=b4.z; bv[j+3]=b4.w;
            }
            #pragma unroll
            for(int i=0;i<8;i++)
            {
                #pragma unroll
                for(int j=0;j<TN;j++) acc[i][j]=fmaf(av8[i],bv[j],acc[i][j]);
            }
        }
        __syncthreads();
    }
    #pragma unroll
    for(int i=0;i<8;i++){
        size_t cro = (size_t)(m0+ty*8+i)*N + n0 + tx*TN;
        #pragma unroll
        for(int j=0;j<TN;j+=4){
            float4 v = make_float4(acc[i][j],acc[i][j+1],acc[i][j+2],acc[i][j+3]);
            if (BIAS){ v.x+=bias[n0+tx*TN+j]; v.y+=bias[n0+tx*TN+j+1];
                       v.z+=bias[n0+tx*TN+j+2]; v.w+=bias[n0+tx*TN+j+3]; }
            if (RELU){ v.x=fmaxf(v.x,0.f); v.y=fmaxf(v.y,0.f); v.z=fmaxf(v.z,0.f); v.w=fmaxf(v.w,0.f); }
            *reinterpret_cast<float4*>(&C[cro+j]) = v;
        }
    }
}

// ---- host ----
extern "C" void kernel_launch(void* const* d_in, const int* in_sizes, int n_in,
                              void* d_out, int out_size)
{
    const float *inp =(const float*)d_in[0], *msk =(const float*)d_in[1];
    const float *adj =(const float*)d_in[2];
    const float *Wp1 =(const float*)d_in[3], *bp1=(const float*)d_in[4];
    const float *Wp2 =(const float*)d_in[5], *bp2=(const float*)d_in[6];
    const float *Wz_f=(const float*)d_in[7], *Wr_f=(const float*)d_in[8], *Wc_f=(const float*)d_in[9];
    const float *bz_f=(const float*)d_in[10],*br_f=(const float*)d_in[11],*bc_f=(const float*)d_in[12];
    const float *Wz_r=(const float*)d_in[13],*Wr_r=(const float*)d_in[14],*Wc_r=(const float*)d_in[15];
    const float *bz_r=(const float*)d_in[16],*br_r=(const float*)d_in[17],*bc_r=(const float*)d_in[18];
    const float *Wd1 =(const float*)d_in[19],*bd1=(const float*)d_in[20];
    const float *Wd2 =(const float*)d_in[21],*bd2=(const float*)d_in[22];
    float* outp = (float*)d_out;

    cudaFuncSetAttribute(tc_gemm, cudaFuncAttributeMaxDynamicSharedMemorySize, TC_DYNSMEM);

    void* vp;
    #define GS(nm) cudaGetSymbolAddress(&vp,nm); float* p_##nm=(float*)vp;
    GS(g_p) GS(g_xp) GS(g_h) GS(g_xh) GS(g_agg) GS(g_zr) GS(g_xrh)
    GS(g_v) GS(g_cl) GS(g_wzr) GS(g_wc) GS(g_hcat) GS(g_s1)
    #undef GS
    cudaGetSymbolAddress(&vp, g_adj_hi); __nv_bfloat16* p_adj_hi=(__nv_bfloat16*)vp;
    cudaGetSymbolAddress(&vp, g_adj_lo); __nv_bfloat16* p_adj_lo=(__nv_bfloat16*)vp;
    cudaGetSymbolAddress(&vp, g_bt_hi);  __nv_bfloat16* p_bt_hi =(__nv_bfloat16*)vp;
    cudaGetSymbolAddress(&vp, g_bt_lo);  __nv_bfloat16* p_bt_lo =(__nv_bfloat16*)vp;

    seq_kernel  <<<ROWS/256,256>>>(inp, msk);
    pproj_kernel<<<ROWS,256>>>(Wp1, bp1);
    sgemm_k<64,false,true><<<dim3(1,ROWS/128,1),256>>>(p_g_p, Wp2, p_g_xp, ROWS,64,256, 0,0,0, bp2);
    zero_h_kernel<<<(L_*2*N_*B_*H_)/256,256>>>();
    pack_w_kernel<<<384,256>>>(Wz_f,Wr_f,Wc_f,Wz_r,Wr_r,Wc_r);
    adjsplit_kernel<<<4096,256>>>(adj);

    for (int t=0; t<T_; t++){
        for (int l=0; l<L_; l++){
            const float *x0,*x1; int nstr,bstr;
            if (l==0){ x0 = p_g_xp + (size_t)t*B_*N_*H_;
                       x1 = p_g_xp + (size_t)(T_-1-t)*B_*N_*H_;
                       nstr = H_; bstr = N_*H_; }
            else     { x0 = p_g_h; x1 = p_g_h + N_*B_*H_;
                       nstr = B_*H_; bstr = H_; }
            float* hbuf = p_g_h + (size_t)l*2*N_*B_*H_;

            build_xh_kernel<<<16384,256>>>(x0,x1,nstr,bstr,hbuf);
            tsplit_kernel<<<dim3(64,32,2),256>>>(p_g_xh, 2048);
            tc_gemm<<<dim3(32,8),256,TC_DYNSMEM>>>(p_adj_hi,p_adj_lo,p_bt_hi,p_bt_lo, p_g_agg, 2048);
            sgemm_k<128,false,false><<<dim3(1,128,2),256>>>(
                p_g_agg, p_g_wzr + l*32768, p_g_zr, 16384,128,128,
                (size_t)1<<21, 16384, (size_t)1<<21, nullptr);
            zr_act_kernel<<<8192,256>>>(x0,x1,nstr,bstr,hbuf,
                bz_f+l*64, bz_r+l*64, br_f+l*64, br_r+l*64);
            sgemm_k<64,false,false><<<dim3(1,128,2),256>>>(
                p_g_xrh, p_g_wc + l*16384, p_g_v, 16384,64,128,
                (size_t)1<<21, 8192, (size_t)1<<20, nullptr);
            tsplit_kernel<<<dim3(32,32,2),256>>>(p_g_v, 1024);
            tc_gemm<<<dim3(16,8),256,TC_DYNSMEM>>>(p_adj_hi,p_adj_lo,p_bt_hi,p_bt_lo, p_g_cl, 1024);
            update_kernel<<<8192,256>>>(hbuf, bc_f+l*64, bc_r+l*64);
        }
    }

    hcat_kernel<<<16384,256>>>();
    sgemm_k<128,true ,true><<<dim3(2,256,1),256>>>(p_g_hcat, Wd1, p_g_s1, 32768,256,128, 0,0,0, bd1);
    sgemm_k<64 ,false,true><<<dim3(1,256,1),256>>>(p_g_s1,  Wd2, outp,  32768,64,256,  0,0,0, bd2);
}

// round 8
// speedup vs baseline: 2.4897x; 1.1896x over previous
#include <cuda_runtime.h>
#include <cuda_bf16.h>
#include <cstdint>

#define T_ 12
#define B_ 16
#define N_ 1024
#define H_ 64
#define L_ 2
#define PROJ_ 256
#define ROWS (T_*B_*N_)
#define HALF (ROWS/2)

// ---- scratch (device globals; allocation-free) ----
__device__ __align__(16) float g_seq [ROWS*2];
__device__ __align__(16) float g_p   [(size_t)ROWS*PROJ_];
__device__ __align__(16) float g_xp  [(size_t)ROWS*H_];
__device__ __align__(16) float g_h   [L_*2*N_*B_*H_];     // [l][d][n][b][64]
__device__ __align__(16) float g_agg [2*N_*B_*128];       // [d][n*16+b][128]
__device__ __align__(16) float g_xrh [2*N_*B_*128];
__device__ __align__(16) float g_v   [2*N_*B_*64];
__device__ __align__(16) float g_z   [2*N_*B_*64];
__device__ __align__(16) float g_wzr [L_*2*128*128];
__device__ __align__(16) float g_wc  [L_*2*128*64];
__device__ __align__(16) float g_hcat[(size_t)L_*B_*N_*128];
__device__ __align__(16) float g_s1  [(size_t)L_*B_*N_*PROJ_];
// bf16-split operands for tensor-core GEMM
__device__ __align__(256) __nv_bfloat16 g_adj_hi[1024*1024];
__device__ __align__(256) __nv_bfloat16 g_adj_lo[1024*1024];
__device__ __align__(256) __nv_bfloat16 g_bt_hi[(size_t)4096*1024];
__device__ __align__(256) __nv_bfloat16 g_bt_lo[(size_t)4096*1024];

// ---- threefry2x32-20, bit-exact JAX normal(key(42)) ----
__device__ __forceinline__ uint32_t rotl_(uint32_t x,int r){return (x<<r)|(x>>(32-r));}
__device__ float tf_noise(unsigned i)
{
    uint32_t x0,x1; bool second = (i >= (unsigned)HALF);
    if(second){x0=i-HALF; x1=i;} else {x0=i; x1=i+HALF;}
    const uint32_t ks0=0u, ks1=42u, ks2=0u^42u^0x1BD11BDAu;
    x0+=ks0; x1+=ks1;
#define TFR(r) {x0+=x1; x1=rotl_(x1,(r)); x1^=x0;}
    TFR(13)TFR(15)TFR(26)TFR(6)  x0+=ks1; x1+=ks2+1u;
    TFR(17)TFR(29)TFR(16)TFR(24) x0+=ks2; x1+=ks0+2u;
    TFR(13)TFR(15)TFR(26)TFR(6)  x0+=ks0; x1+=ks1+3u;
    TFR(17)TFR(29)TFR(16)TFR(24) x0+=ks1; x1+=ks2+4u;
    TFR(13)TFR(15)TFR(26)TFR(6)  x0+=ks2; x1+=ks0+5u;
#undef TFR
    uint32_t bits = second ? x1 : x0;
    float f = __uint_as_float((bits>>9)|0x3f800000u) - 1.0f;
    const float lo = -0.99999994f;
    float u = fmaxf(lo, fmaf(f, 2.0f, lo));
    return 1.41421356f * erfinvf(u) * 0.01f;
}

__device__ __forceinline__ float sig_(float x){ return 1.f/(1.f + expf(-x)); }

// ---- elementwise kernels ----
__global__ void seq_kernel(const float* __restrict__ in, const float* __restrict__ mk)
{
    unsigned i = blockIdx.x*256u + threadIdx.x;
    reinterpret_cast<float2*>(g_seq)[i] = make_float2(in[i] + tf_noise(i), mk[i]);
}

__global__ void pproj_kernel(const float* __restrict__ Wp1, const float* __restrict__ bp1)
{
    size_t gid = (size_t)blockIdx.x*256u + threadIdx.x;
    int j = (int)(gid & 255u); size_t row = gid >> 8;
    float2 s = reinterpret_cast<const float2*>(g_seq)[row];
    g_p[gid] = fmaxf(fmaf(s.x, Wp1[j], fmaf(s.y, Wp1[256+j], bp1[j])), 0.f);
}

__global__ void zero_h_kernel(){ g_h[blockIdx.x*256u + threadIdx.x] = 0.f; }

__global__ void pack_w_kernel(const float* Wz_f,const float* Wr_f,const float* Wc_f,
                              const float* Wz_r,const float* Wr_r,const float* Wc_r)
{
    unsigned idx = blockIdx.x*256u + threadIdx.x;
    if (idx < 65536u) {
        int col=idx&127, f=(idx>>7)&127, d=(idx>>14)&1, l=idx>>15;
        const float* Wz = d?Wz_r:Wz_f; const float* Wr = d?Wr_r:Wr_f;
        g_wzr[idx] = (col<64) ? Wz[(l*128+f)*64+col] : Wr[(l*128+f)*64+(col-64)];
    } else {
        unsigned k = idx - 65536u;
        int j=k&63, f=(k>>6)&127, d=(k>>13)&1, l=k>>14;
        g_wc[k] = (d?Wc_r:Wc_f)[(l*128+f)*64+j];
    }
}

__global__ void hcat_kernel()
{
    unsigned idx = blockIdx.x*256u + threadIdx.x;
    int jj=idx&127, n=(idx>>7)&1023, b=(idx>>17)&15, l=idx>>21;
    int d=jj>>6, h=jj&63;
    g_hcat[idx] = g_h[((((size_t)l*2 + d)*N_ + n)*B_ + b)*H_ + h];
}

// ---- bf16 split helpers ----
__global__ void adjsplit_kernel(const float* __restrict__ adj)
{
    unsigned i = blockIdx.x*256u + threadIdx.x;
    float a = adj[i];
    __nv_bfloat16 h = __float2bfloat16_rn(a);
    g_adj_hi[i] = h;
    g_adj_lo[i] = __float2bfloat16_rn(a - __bfloat162float(h));
}

// fused build_xh + transpose + split:
// bt[(d*2048 + c)*1024 + n] = xh(d,n,c) where c=b*128+f; f<64 -> x, f>=64 -> h
__global__ void btsplit_xh(const float* __restrict__ x0, const float* __restrict__ x1,
                           int nstr, int bstr, const float* __restrict__ hbuf)
{
    __shared__ float tile[32][33];
    int d = blockIdx.z;
    int c0 = blockIdx.x*32, n0 = blockIdx.y*32;
    int tx = threadIdx.x & 31, ty = threadIdx.x >> 5;
    int b = c0 >> 7, f0 = c0 & 127;
    const float* xb = d ? x1 : x0;
    #pragma unroll
    for (int i=0;i<4;i++){
        int n = n0 + ty + 8*i;
        int f = f0 + tx;
        float v;
        if (f < 64) v = xb[(size_t)n*nstr + (size_t)b*bstr + f];
        else        v = hbuf[(((size_t)d*1024 + n)*16 + b)*64 + (f-64)];
        tile[ty+8*i][tx] = v;
    }
    __syncthreads();
    size_t ob = ((size_t)(d*2048 + c0))*1024 + n0;
    #pragma unroll
    for (int i=0;i<4;i++){
        int c = ty + 8*i;
        float v = tile[tx][c];
        __nv_bfloat16 h = __float2bfloat16_rn(v);
        g_bt_hi[ob + (size_t)c*1024 + tx] = h;
        g_bt_lo[ob + (size_t)c*1024 + tx] = __float2bfloat16_rn(v - __bfloat162float(h));
    }
}

// transpose + split of g_v: src[(d*1024+n)*1024 + c] -> bt[(d*1024+c)*1024 + n]
__global__ void tsplit_v()
{
    __shared__ float tile[32][33];
    int d = blockIdx.z;
    int c0 = blockIdx.x*32, n0 = blockIdx.y*32;
    int tx = threadIdx.x & 31, ty = threadIdx.x >> 5;
    const float* s = g_v + ((size_t)(d*1024 + n0))*1024 + c0;
    #pragma unroll
    for (int i=0;i<4;i++)
        tile[ty+8*i][tx] = s[(size_t)(ty+8*i)*1024 + tx];
    __syncthreads();
    size_t ob = ((size_t)(d*1024 + c0))*1024 + n0;
    #pragma unroll
    for (int i=0;i<4;i++){
        int c = ty + 8*i;
        float v = tile[tx][c];
        __nv_bfloat16 h = __float2bfloat16_rn(v);
        g_bt_hi[ob + (size_t)c*1024 + tx] = h;
        g_bt_lo[ob + (size_t)c*1024 + tx] = __float2bfloat16_rn(v - __bfloat162float(h));
    }
}

// ---- tensor-core split-bf16 GEMM ----
__device__ __forceinline__ uint32_t smem_u32_(const void* p){
    uint32_t a;
    asm("{ .reg .u64 t; cvta.to.shared.u64 t, %1; cvt.u32.u64 %0, t; }":"=r"(a):"l"(p));
    return a;
}
#define LDSM_X4(r0,r1,r2,r3,addr) \
    asm volatile("ldmatrix.sync.aligned.m8n8.x4.shared.b16 {%0,%1,%2,%3}, [%4];" \
        : "=r"(r0),"=r"(r1),"=r"(r2),"=r"(r3) : "r"(addr))
#define MMA16816(d0,d1,d2,d3,a0,a1,a2,a3,b0,b1) \
    asm volatile("mma.sync.aligned.m16n8k16.row.col.f32.bf16.bf16.f32 " \
        "{%0,%1,%2,%3}, {%4,%5,%6,%7}, {%8,%9}, {%0,%1,%2,%3};" \
        : "+f"(d0),"+f"(d1),"+f"(d2),"+f"(d3) \
        : "r"(a0),"r"(a1),"r"(a2),"r"(a3),"r"(b0),"r"(b1))
#define CP16(dst,src) asm volatile("cp.async.cg.shared.global [%0], [%1], 16;"::"r"(dst),"l"(src))

#define TC_DYNSMEM 131072   // 2 stages x (Ahi+Alo+Bhi+Blo = 64KB)

__device__ __forceinline__ void tc_load_stage4(
    int kc, uint32_t sbuf,
    const __nv_bfloat16* __restrict__ Ahi, const __nv_bfloat16* __restrict__ Alo,
    const __nv_bfloat16* __restrict__ Bhi, const __nv_bfloat16* __restrict__ Blo,
    int m0, int n0, int tid)
{
    int koff = kc*64;
    const __nv_bfloat16* gs[4] = {Ahi, Alo, Bhi, Blo};
    #pragma unroll
    for (int t=0;t<4;t++){
        int rbase = (t<2) ? m0 : n0;
        const __nv_bfloat16* g = gs[t];
        #pragma unroll
        for (int i=0;i<4;i++){
            int idx = tid + 256*i;            // 0..1023 = 128 rows x 8 segs
            int row = idx >> 3, seg = idx & 7;
            uint32_t sw = (uint32_t)((seg ^ (row & 7)) << 4);
            uint32_t dst = sbuf + (uint32_t)t*16384u + (uint32_t)(row*128) + sw;
            CP16(dst, (const void*)(g + (size_t)(rbase+row)*1024 + koff + seg*8));
        }
    }
    asm volatile("cp.async.commit_group;");
}

// EPI=0: Cout[(d*1024+m)*Wd + colbase+nc] = acc   (d = n0/Wd)
// EPI=1: GRU update: c=tanh(acc+bc); h = z*h+(1-z)*c  (Wd=1024, col = b*64+j)
template<int EPI>
__global__ __launch_bounds__(256,1)
void tc_gemm(const __nv_bfloat16* __restrict__ Ahi, const __nv_bfloat16* __restrict__ Alo,
             const __nv_bfloat16* __restrict__ Bhi, const __nv_bfloat16* __restrict__ Blo,
             float* __restrict__ Cout, int Wd,
             const float* __restrict__ bc0, const float* __restrict__ bc1,
             float* __restrict__ hbuf, const float* __restrict__ zbuf)
{
    extern __shared__ __align__(128) char dyn_[];
    uint32_t sbase = smem_u32_(dyn_);
    const int tid = threadIdx.x, wid = tid>>5, lane = tid&31;
    const int mw = (wid>>2)*64, nw = (wid&3)*32;
    const int m0 = blockIdx.y*128, n0 = blockIdx.x*128;

    float acc[4][4][4];
    #pragma unroll
    for (int i=0;i<4;i++)
        #pragma unroll
        for (int j=0;j<4;j++)
            #pragma unroll
            for (int q=0;q<4;q++) acc[i][j][q]=0.f;

    tc_load_stage4(0, sbase, Ahi,Alo,Bhi,Blo, m0,n0, tid);

    for (int c=0;c<16;c++){
        uint32_t buf = (uint32_t)(c & 1);
        if (c+1 < 16){
            tc_load_stage4(c+1, sbase + (buf^1u)*65536u, Ahi,Alo,Bhi,Blo, m0,n0, tid);
            asm volatile("cp.async.wait_group 1;");
        } else {
            asm volatile("cp.async.wait_group 0;");
        }
        __syncthreads();

        uint32_t sA = sbase + buf*65536u;
        #pragma unroll
        for (int ks=0; ks<4; ks++){
            uint32_t aH[4][4], aL[4][4], bH[2][4], bL[2][4];
            #pragma unroll
            for (int tm=0;tm<4;tm++){
                int row = mw + tm*16 + ((lane>>3)&1)*8 + (lane&7);
                int ksg = ks*2 + (lane>>4);
                uint32_t off = (uint32_t)(row*128) + (uint32_t)(((ksg ^ (row&7)))<<4);
                LDSM_X4(aH[tm][0],aH[tm][1],aH[tm][2],aH[tm][3], sA + off);
                LDSM_X4(aL[tm][0],aL[tm][1],aL[tm][2],aL[tm][3], sA + 16384u + off);
            }
            #pragma unroll
            for (int np=0;np<2;np++){
                int row = nw + np*16 + ((lane>>4)&1)*8 + (lane&7);
                int ksg = ks*2 + ((lane>>3)&1);
                uint32_t off = (uint32_t)(row*128) + (uint32_t)(((ksg ^ (row&7)))<<4);
                LDSM_X4(bH[np][0],bH[np][1],bH[np][2],bH[np][3], sA + 32768u + off);
                LDSM_X4(bL[np][0],bL[np][1],bL[np][2],bL[np][3], sA + 49152u + off);
            }
            #pragma unroll
            for (int tm=0;tm<4;tm++)
            {
                #pragma unroll
                for (int tn=0;tn<4;tn++){
                    int hi0 = (tn&1)?2:0, hi1 = (tn&1)?3:1, g = tn>>1;
                    MMA16816(acc[tm][tn][0],acc[tm][tn][1],acc[tm][tn][2],acc[tm][tn][3],
                             aH[tm][0],aH[tm][1],aH[tm][2],aH[tm][3], bH[g][hi0],bH[g][hi1]);
                    MMA16816(acc[tm][tn][0],acc[tm][tn][1],acc[tm][tn][2],acc[tm][tn][3],
                             aH[tm][0],aH[tm][1],aH[tm][2],aH[tm][3], bL[g][hi0],bL[g][hi1]);
                    MMA16816(acc[tm][tn][0],acc[tm][tn][1],acc[tm][tn][2],acc[tm][tn][3],
                             aL[tm][0],aL[tm][1],aL[tm][2],aL[tm][3], bH[g][hi0],bH[g][hi1]);
                }
            }
        }
        __syncthreads();
    }

    const int d = n0 / Wd;
    if (EPI == 0){
        #pragma unroll
        for (int tm=0;tm<4;tm++)
        {
            #pragma unroll
            for (int tn=0;tn<4;tn++){
                int m = m0 + mw + tm*16 + (lane>>2);
                int nc = (n0 % Wd) + nw + tn*8 + (lane&3)*2;
                float* o0 = Cout + ((size_t)(d*1024 + m))*(size_t)Wd + nc;
                *reinterpret_cast<float2*>(o0) = make_float2(acc[tm][tn][0], acc[tm][tn][1]);
                float* o1 = o0 + (size_t)8*(size_t)Wd;
                *reinterpret_cast<float2*>(o1) = make_float2(acc[tm][tn][2], acc[tm][tn][3]);
            }
        }
    } else {
        const float* bc = d ? bc1 : bc0;
        #pragma unroll
        for (int tm=0;tm<4;tm++)
        {
            #pragma unroll
            for (int tn=0;tn<4;tn++){
                int m = m0 + mw + tm*16 + (lane>>2);
                int nc = (n0 & 1023) + nw + tn*8 + (lane&3)*2;
                int b = nc>>6, j = nc&63;
                float bj0 = bc[j], bj1 = bc[j+1];
                size_t h0 = (((size_t)(d*1024 + m))*16 + b)*64 + j;
                {
                    float2 hv = *reinterpret_cast<float2*>(hbuf + h0);
                    float2 zv = *reinterpret_cast<const float2*>(zbuf + h0);
                    float c0 = tanhf(acc[tm][tn][0] + bj0);
                    float c1 = tanhf(acc[tm][tn][1] + bj1);
                    *reinterpret_cast<float2*>(hbuf + h0) =
                        make_float2(zv.x*hv.x + (1.f-zv.x)*c0, zv.y*hv.y + (1.f-zv.y)*c1);
                }
                {
                    size_t h1 = h0 + 8*16*64;
                    float2 hv = *reinterpret_cast<float2*>(hbuf + h1);
                    float2 zv = *reinterpret_cast<const float2*>(zbuf + h1);
                    float c0 = tanhf(acc[tm][tn][2] + bj0);
                    float c1 = tanhf(acc[tm][tn][3] + bj1);
                    *reinterpret_cast<float2*>(hbuf + h1) =
                        make_float2(zv.x*hv.x + (1.f-zv.x)*c0, zv.y*hv.y + (1.f-zv.y)*c1);
                }
            }
        }
    }
}

// ---- register-tiled fp32 SGEMM (validated) ----
template<int BN, bool RELU, bool BIAS>
__global__ __launch_bounds__(256)
void sgemm_k(const float* __restrict__ A, const float* __restrict__ Bm,
             float* __restrict__ C, int M, int N, int K,
             size_t sAz, size_t sBz, size_t sCz, const float* __restrict__ bias)
{
    constexpr int TN = BN/16;
    __shared__ float As[8][128];
    __shared__ float Bs[8][BN];
    const int tid=threadIdx.x, tx=tid&15, ty=tid>>4;
    const int m0=blockIdx.y*128, n0=blockIdx.x*BN;
    A += (size_t)blockIdx.z*sAz; Bm += (size_t)blockIdx.z*sBz; C += (size_t)blockIdx.z*sCz;

    float acc[8][TN];
    #pragma unroll
    for(int i=0;i<8;i++)
    {
        #pragma unroll
        for(int j=0;j<TN;j++) acc[i][j]=0.f;
    }

    const int arow=tid>>1, ak=(tid&1)*4, br=tid>>5;
    for(int kt=0; kt<K; kt+=8){
        float4 av = *reinterpret_cast<const float4*>(A + (size_t)(m0+arow)*K + kt + ak);
        As[ak+0][arow]=av.x; As[ak+1][arow]=av.y; As[ak+2][arow]=av.z; As[ak+3][arow]=av.w;
        if (BN==128){
            int bc=(tid&31)*4;
            float4 bv = *reinterpret_cast<const float4*>(Bm + (size_t)(kt+br)*N + n0 + bc);
            *reinterpret_cast<float4*>(&Bs[br][bc]) = bv;
        } else {
            int bc=(tid&31)*2;
            float2 bv = *reinterpret_cast<const float2*>(Bm + (size_t)(kt+br)*N + n0 + bc);
            *reinterpret_cast<float2*>(&Bs[br][bc]) = bv;
        }
        __syncthreads();
        #pragma unroll
        for(int k=0;k<8;k++){
            float4 a0 = *reinterpret_cast<const float4*>(&As[k][ty*8]);
            float4 a1 = *reinterpret_cast<const float4*>(&As[k][ty*8+4]);
            float av8[8]={a0.x,a0.y,a0.z,a0.w,a1.x,a1.y,a1.z,a1.w};
            float bv[TN];
            #pragma unroll
            for(int j=0;j<TN;j+=4){
                float4 b4 = *reinterpret_cast<const float4*>(&Bs[k][tx*TN+j]);
                bv[j]=b4.x; bv[j+1]=b4.y; bv[j+2]=b4.z; bv[j+3]=b4.w;
            }
            #pragma unroll
            for(int i=0;i<8;i++)
            {
                #pragma unroll
                for(int j=0;j<TN;j++) acc[i][j]=fmaf(av8[i],bv[j],acc[i][j]);
            }
        }
        __syncthreads();
    }
    #pragma unroll
    for(int i=0;i<8;i++){
        size_t cro = (size_t)(m0+ty*8+i)*N + n0 + tx*TN;
        #pragma unroll
        for(int j=0;j<TN;j+=4){
            float4 v = make_float4(acc[i][j],acc[i][j+1],acc[i][j+2],acc[i][j+3]);
            if (BIAS){ v.x+=bias[n0+tx*TN+j]; v.y+=bias[n0+tx*TN+j+1];
                       v.z+=bias[n0+tx*TN+j+2]; v.w+=bias[n0+tx*TN+j+3]; }
            if (RELU){ v.x=fmaxf(v.x,0.f); v.y=fmaxf(v.y,0.f); v.z=fmaxf(v.z,0.f); v.w=fmaxf(v.w,0.f); }
            *reinterpret_cast<float4*>(&C[cro+j]) = v;
        }
    }
}

// ---- fused zr GEMM: zr = agg@Wzr (+bias, sigmoid); writes g_z and g_xrh ----
__global__ __launch_bounds__(256)
void sgemm_zr(const float* __restrict__ A, const float* __restrict__ Bm,
              const float* __restrict__ x0, const float* __restrict__ x1,
              int nstr, int bstr, const float* __restrict__ hbuf,
              const float* __restrict__ bz0, const float* __restrict__ bz1,
              const float* __restrict__ br0, const float* __restrict__ br1)
{
    __shared__ float As[8][128];
    __shared__ float Bs[8][128];
    const int tid=threadIdx.x, tx=tid&15, ty=tid>>4;
    const int m0=blockIdx.y*128;
    const int d = blockIdx.z;
    A += (size_t)d<<21; Bm += (size_t)d*16384;

    float acc[8][8];
    #pragma unroll
    for(int i=0;i<8;i++)
    {
        #pragma unroll
        for(int j=0;j<8;j++) acc[i][j]=0.f;
    }

    const int arow=tid>>1, ak=(tid&1)*4, br=tid>>5;
    for(int kt=0; kt<128; kt+=8){
        float4 av = *reinterpret_cast<const float4*>(A + (size_t)(m0+arow)*128 + kt + ak);
        As[ak+0][arow]=av.x; As[ak+1][arow]=av.y; As[ak+2][arow]=av.z; As[ak+3][arow]=av.w;
        int bc=(tid&31)*4;
        float4 bv = *reinterpret_cast<const float4*>(Bm + (size_t)(kt+br)*128 + bc);
        *reinterpret_cast<float4*>(&Bs[br][bc]) = bv;
        __syncthreads();
        #pragma unroll
        for(int k=0;k<8;k++){
            float4 a0 = *reinterpret_cast<const float4*>(&As[k][ty*8]);
            float4 a1 = *reinterpret_cast<const float4*>(&As[k][ty*8+4]);
            float av8[8]={a0.x,a0.y,a0.z,a0.w,a1.x,a1.y,a1.z,a1.w};
            float bv8[8];
            #pragma unroll
            for(int j=0;j<8;j+=4){
                float4 b4 = *reinterpret_cast<const float4*>(&Bs[k][tx*8+j]);
                bv8[j]=b4.x; bv8[j+1]=b4.y; bv8[j+2]=b4.z; bv8[j+3]=b4.w;
            }
            #pragma unroll
            for(int i=0;i<8;i++)
            {
                #pragma unroll
                for(int j=0;j<8;j++) acc[i][j]=fmaf(av8[i],bv8[j],acc[i][j]);
            }
        }
        __syncthreads();
    }

    const float* xb  = d ? x1 : x0;
    const float* bzp = d ? bz1 : bz0;
    const float* brp = d ? br1 : br0;
    #pragma unroll
    for(int i=0;i<8;i++){
        int row = m0 + ty*8 + i;         // 0..16383 within dir
        int n = row>>4, b = row&15;
        size_t rg = ((size_t)d<<14) + row;
        if (tx < 8){
            // z-half: cols jj = tx*8..tx*8+7 < 64
            #pragma unroll
            for(int j=0;j<8;j+=4){
                int jj = tx*8+j;
                float4 bz4 = *reinterpret_cast<const float4*>(bzp + jj);
                float4 zv = make_float4(sig_(acc[i][j]+bz4.x),   sig_(acc[i][j+1]+bz4.y),
                                        sig_(acc[i][j+2]+bz4.z), sig_(acc[i][j+3]+bz4.w));
                *reinterpret_cast<float4*>(g_z + rg*64 + jj) = zv;
                float4 xv = *reinterpret_cast<const float4*>(xb + (size_t)n*nstr + (size_t)b*bstr + jj);
                *reinterpret_cast<float4*>(g_xrh + rg*128 + jj) = xv;
            }
        } else {
            // r-half: cols jj >= 64
            #pragma unroll
            for(int j=0;j<8;j+=4){
                int jj = tx*8+j, j2 = jj-64;
                float4 br4 = *reinterpret_cast<const float4*>(brp + j2);
                float4 hv = *reinterpret_cast<const float4*>(hbuf + rg*64 + j2);
                float4 rv = make_float4(sig_(acc[i][j]+br4.x)*hv.x,   sig_(acc[i][j+1]+br4.y)*hv.y,
                                        sig_(acc[i][j+2]+br4.z)*hv.z, sig_(acc[i][j+3]+br4.w)*hv.w);
                *reinterpret_cast<float4*>(g_xrh + rg*128 + jj) = rv;
            }
        }
    }
}

// ---- host ----
extern "C" void kernel_launch(void* const* d_in, const int* in_sizes, int n_in,
                              void* d_out, int out_size)
{
    const float *inp =(const float*)d_in[0], *msk =(const float*)d_in[1];
    const float *adj =(const float*)d_in[2];
    const float *Wp1 =(const float*)d_in[3], *bp1=(const float*)d_in[4];
    const float *Wp2 =(const float*)d_in[5], *bp2=(const float*)d_in[6];
    const float *Wz_f=(const float*)d_in[7], *Wr_f=(const float*)d_in[8], *Wc_f=(const float*)d_in[9];
    const float *bz_f=(const float*)d_in[10],*br_f=(const float*)d_in[11],*bc_f=(const float*)d_in[12];
    const float *Wz_r=(const float*)d_in[13],*Wr_r=(const float*)d_in[14],*Wc_r=(const float*)d_in[15];
    const float *bz_r=(const float*)d_in[16],*br_r=(const float*)d_in[17],*bc_r=(const float*)d_in[18];
    const float *Wd1 =(const float*)d_in[19],*bd1=(const float*)d_in[20];
    const float *Wd2 =(const float*)d_in[21],*bd2=(const float*)d_in[22];
    float* outp = (float*)d_out;

    cudaFuncSetAttribute(tc_gemm<0>, cudaFuncAttributeMaxDynamicSharedMemorySize, TC_DYNSMEM);
    cudaFuncSetAttribute(tc_gemm<1>, cudaFuncAttributeMaxDynamicSharedMemorySize, TC_DYNSMEM);

    void* vp;
    #define GS(nm) cudaGetSymbolAddress(&vp,nm); float* p_##nm=(float*)vp;
    GS(g_p) GS(g_xp) GS(g_h) GS(g_agg) GS(g_xrh)
    GS(g_v) GS(g_z) GS(g_wzr) GS(g_wc) GS(g_hcat) GS(g_s1)
    #undef GS
    cudaGetSymbolAddress(&vp, g_adj_hi); __nv_bfloat16* p_adj_hi=(__nv_bfloat16*)vp;
    cudaGetSymbolAddress(&vp, g_adj_lo); __nv_bfloat16* p_adj_lo=(__nv_bfloat16*)vp;
    cudaGetSymbolAddress(&vp, g_bt_hi);  __nv_bfloat16* p_bt_hi =(__nv_bfloat16*)vp;
    cudaGetSymbolAddress(&vp, g_bt_lo);  __nv_bfloat16* p_bt_lo =(__nv_bfloat16*)vp;

    seq_kernel  <<<ROWS/256,256>>>(inp, msk);
    pproj_kernel<<<ROWS,256>>>(Wp1, bp1);
    sgemm_k<64,false,true><<<dim3(1,ROWS/128,1),256>>>(p_g_p, Wp2, p_g_xp, ROWS,64,256, 0,0,0, bp2);
    zero_h_kernel<<<(L_*2*N_*B_*H_)/256,256>>>();
    pack_w_kernel<<<384,256>>>(Wz_f,Wr_f,Wc_f,Wz_r,Wr_r,Wc_r);
    adjsplit_kernel<<<4096,256>>>(adj);

    for (int t=0; t<T_; t++){
        for (int l=0; l<L_; l++){
            const float *x0,*x1; int nstr,bstr;
            if (l==0){ x0 = p_g_xp + (size_t)t*B_*N_*H_;
                       x1 = p_g_xp + (size_t)(T_-1-t)*B_*N_*H_;
                       nstr = H_; bstr = N_*H_; }
            else     { x0 = p_g_h; x1 = p_g_h + N_*B_*H_;
                       nstr = B_*H_; bstr = H_; }
            float* hbuf = p_g_h + (size_t)l*2*N_*B_*H_;

            btsplit_xh<<<dim3(64,32,2),256>>>(x0,x1,nstr,bstr,hbuf);
            tc_gemm<0><<<dim3(32,8),256,TC_DYNSMEM>>>(
                p_adj_hi,p_adj_lo,p_bt_hi,p_bt_lo, p_g_agg, 2048,
                nullptr,nullptr,nullptr,nullptr);
            sgemm_zr<<<dim3(1,128,2),256>>>(
                p_g_agg, p_g_wzr + l*32768,
                x0,x1,nstr,bstr, hbuf,
                bz_f+l*64, bz_r+l*64, br_f+l*64, br_r+l*64);
            sgemm_k<64,false,false><<<dim3(1,128,2),256>>>(
                p_g_xrh, p_g_wc + l*16384, p_g_v, 16384,64,128,
                (size_t)1<<21, 8192, (size_t)1<<20, nullptr);
            tsplit_v<<<dim3(32,32,2),256>>>();
            tc_gemm<1><<<dim3(16,8),256,TC_DYNSMEM>>>(
                p_adj_hi,p_adj_lo,p_bt_hi,p_bt_lo, nullptr, 1024,
                bc_f+l*64, bc_r+l*64, hbuf, p_g_z);
        }
    }

    hcat_kernel<<<16384,256>>>();
    sgemm_k<128,true ,true><<<dim3(2,256,1),256>>>(p_g_hcat, Wd1, p_g_s1, 32768,256,128, 0,0,0, bd1);
    sgemm_k<64 ,false,true><<<dim3(1,256,1),256>>>(p_g_s1,  Wd2, outp,  32768,64,256,  0,0,0, bd2);
}

// round 9
// speedup vs baseline: 2.5360x; 1.0186x over previous
#include <cuda_runtime.h>
#include <cuda_bf16.h>
#include <cstdint>

#define T_ 12
#define B_ 16
#define N_ 1024
#define H_ 64
#define L_ 2
#define PROJ_ 256
#define ROWS (T_*B_*N_)
#define HALF (ROWS/2)

// ---- scratch (device globals; allocation-free) ----
__device__ __align__(16) float g_seq [ROWS*2];
__device__ __align__(16) float g_p   [(size_t)ROWS*PROJ_];
__device__ __align__(16) float g_xp  [(size_t)ROWS*H_];
__device__ __align__(16) float g_h   [L_*2*N_*B_*H_];     // [l][d][n][b][64]
__device__ __align__(16) float g_agg [2*N_*B_*128];       // [d][n*16+b][128]
__device__ __align__(16) float g_xrh [2*N_*B_*128];
__device__ __align__(16) float g_z   [2*N_*B_*64];
__device__ __align__(16) float g_wzr [L_*2*128*128];
__device__ __align__(16) float g_wc  [L_*2*128*64];
__device__ __align__(16) float g_hcat[(size_t)L_*B_*N_*128];
__device__ __align__(16) float g_s1  [(size_t)L_*B_*N_*PROJ_];
// bf16-split operands for tensor-core GEMM
__device__ __align__(256) __nv_bfloat16 g_adj_hi[1024*1024];
__device__ __align__(256) __nv_bfloat16 g_adj_lo[1024*1024];
__device__ __align__(256) __nv_bfloat16 g_bt_hi[(size_t)4096*1024];
__device__ __align__(256) __nv_bfloat16 g_bt_lo[(size_t)4096*1024];

// ---- threefry2x32-20, bit-exact JAX normal(key(42)) ----
__device__ __forceinline__ uint32_t rotl_(uint32_t x,int r){return (x<<r)|(x>>(32-r));}
__device__ float tf_noise(unsigned i)
{
    uint32_t x0,x1; bool second = (i >= (unsigned)HALF);
    if(second){x0=i-HALF; x1=i;} else {x0=i; x1=i+HALF;}
    const uint32_t ks0=0u, ks1=42u, ks2=0u^42u^0x1BD11BDAu;
    x0+=ks0; x1+=ks1;
#define TFR(r) {x0+=x1; x1=rotl_(x1,(r)); x1^=x0;}
    TFR(13)TFR(15)TFR(26)TFR(6)  x0+=ks1; x1+=ks2+1u;
    TFR(17)TFR(29)TFR(16)TFR(24) x0+=ks2; x1+=ks0+2u;
    TFR(13)TFR(15)TFR(26)TFR(6)  x0+=ks0; x1+=ks1+3u;
    TFR(17)TFR(29)TFR(16)TFR(24) x0+=ks1; x1+=ks2+4u;
    TFR(13)TFR(15)TFR(26)TFR(6)  x0+=ks2; x1+=ks0+5u;
#undef TFR
    uint32_t bits = second ? x1 : x0;
    float f = __uint_as_float((bits>>9)|0x3f800000u) - 1.0f;
    const float lo = -0.99999994f;
    float u = fmaxf(lo, fmaf(f, 2.0f, lo));
    return 1.41421356f * erfinvf(u) * 0.01f;
}

__device__ __forceinline__ float sig_(float x){ return 1.f/(1.f + expf(-x)); }

// ---- elementwise kernels ----
__global__ void seq_kernel(const float* __restrict__ in, const float* __restrict__ mk)
{
    unsigned i = blockIdx.x*256u + threadIdx.x;
    reinterpret_cast<float2*>(g_seq)[i] = make_float2(in[i] + tf_noise(i), mk[i]);
}

__global__ void pproj_kernel(const float* __restrict__ Wp1, const float* __restrict__ bp1)
{
    size_t gid = (size_t)blockIdx.x*256u + threadIdx.x;
    int j = (int)(gid & 255u); size_t row = gid >> 8;
    float2 s = reinterpret_cast<const float2*>(g_seq)[row];
    g_p[gid] = fmaxf(fmaf(s.x, Wp1[j], fmaf(s.y, Wp1[256+j], bp1[j])), 0.f);
}

__global__ void zero_h_kernel(){ g_h[blockIdx.x*256u + threadIdx.x] = 0.f; }

__global__ void pack_w_kernel(const float* Wz_f,const float* Wr_f,const float* Wc_f,
                              const float* Wz_r,const float* Wr_r,const float* Wc_r)
{
    unsigned idx = blockIdx.x*256u + threadIdx.x;
    if (idx < 65536u) {
        int col=idx&127, f=(idx>>7)&127, d=(idx>>14)&1, l=idx>>15;
        const float* Wz = d?Wz_r:Wz_f; const float* Wr = d?Wr_r:Wr_f;
        g_wzr[idx] = (col<64) ? Wz[(l*128+f)*64+col] : Wr[(l*128+f)*64+(col-64)];
    } else {
        unsigned k = idx - 65536u;
        int j=k&63, f=(k>>6)&127, d=(k>>13)&1, l=k>>14;
        g_wc[k] = (d?Wc_r:Wc_f)[(l*128+f)*64+j];
    }
}

__global__ void hcat_kernel()
{
    unsigned idx = blockIdx.x*256u + threadIdx.x;
    int jj=idx&127, n=(idx>>7)&1023, b=(idx>>17)&15, l=idx>>21;
    int d=jj>>6, h=jj&63;
    g_hcat[idx] = g_h[((((size_t)l*2 + d)*N_ + n)*B_ + b)*H_ + h];
}

// ---- bf16 split helpers ----
__global__ void adjsplit_kernel(const float* __restrict__ adj)
{
    unsigned i = blockIdx.x*256u + threadIdx.x;
    float a = adj[i];
    __nv_bfloat16 h = __float2bfloat16_rn(a);
    g_adj_hi[i] = h;
    g_adj_lo[i] = __float2bfloat16_rn(a - __bfloat162float(h));
}

// fused build_xh + transpose + split:
// bt[(d*2048 + c)*1024 + n] = xh(d,n,c) where c=b*128+f; f<64 -> x, f>=64 -> h
__global__ void btsplit_xh(const float* __restrict__ x0, const float* __restrict__ x1,
                           int nstr, int bstr, const float* __restrict__ hbuf)
{
    __shared__ float tile[32][33];
    int d = blockIdx.z;
    int c0 = blockIdx.x*32, n0 = blockIdx.y*32;
    int tx = threadIdx.x & 31, ty = threadIdx.x >> 5;
    int b = c0 >> 7, f0 = c0 & 127;
    const float* xb = d ? x1 : x0;
    #pragma unroll
    for (int i=0;i<4;i++){
        int n = n0 + ty + 8*i;
        int f = f0 + tx;
        float v;
        if (f < 64) v = xb[(size_t)n*nstr + (size_t)b*bstr + f];
        else        v = hbuf[(((size_t)d*1024 + n)*16 + b)*64 + (f-64)];
        tile[ty+8*i][tx] = v;
    }
    __syncthreads();
    size_t ob = ((size_t)(d*2048 + c0))*1024 + n0;
    #pragma unroll
    for (int i=0;i<4;i++){
        int c = ty + 8*i;
        float v = tile[tx][c];
        __nv_bfloat16 h = __float2bfloat16_rn(v);
        g_bt_hi[ob + (size_t)c*1024 + tx] = h;
        g_bt_lo[ob + (size_t)c*1024 + tx] = __float2bfloat16_rn(v - __bfloat162float(h));
    }
}

// ---- tensor-core split-bf16 GEMM ----
__device__ __forceinline__ uint32_t smem_u32_(const void* p){
    uint32_t a;
    asm("{ .reg .u64 t; cvta.to.shared.u64 t, %1; cvt.u32.u64 %0, t; }":"=r"(a):"l"(p));
    return a;
}
#define LDSM_X4(r0,r1,r2,r3,addr) \
    asm volatile("ldmatrix.sync.aligned.m8n8.x4.shared.b16 {%0,%1,%2,%3}, [%4];" \
        : "=r"(r0),"=r"(r1),"=r"(r2),"=r"(r3) : "r"(addr))
#define MMA16816(d0,d1,d2,d3,a0,a1,a2,a3,b0,b1) \
    asm volatile("mma.sync.aligned.m16n8k16.row.col.f32.bf16.bf16.f32 " \
        "{%0,%1,%2,%3}, {%4,%5,%6,%7}, {%8,%9}, {%0,%1,%2,%3};" \
        : "+f"(d0),"+f"(d1),"+f"(d2),"+f"(d3) \
        : "r"(a0),"r"(a1),"r"(a2),"r"(a3),"r"(b0),"r"(b1))
#define CP16(dst,src) asm volatile("cp.async.cg.shared.global [%0], [%1], 16;"::"r"(dst),"l"(src))

template<int BN>
__device__ __forceinline__ void tc_load_stage4(
    int kc, uint32_t sbuf,
    const __nv_bfloat16* __restrict__ Ahi, const __nv_bfloat16* __restrict__ Alo,
    const __nv_bfloat16* __restrict__ Bhi, const __nv_bfloat16* __restrict__ Blo,
    int m0, int n0, int tid)
{
    constexpr uint32_t SZB = (uint32_t)BN*128u;
    int koff = kc*64;
    #pragma unroll
    for (int t=0;t<2;t++){
        const __nv_bfloat16* g = t ? Alo : Ahi;
        #pragma unroll
        for (int i=0;i<4;i++){
            int idx = tid + 256*i;            // 128 rows x 8 segs
            int row = idx >> 3, seg = idx & 7;
            uint32_t sw = (uint32_t)((seg ^ (row & 7)) << 4);
            CP16(sbuf + (uint32_t)t*16384u + (uint32_t)(row*128) + sw,
                 (const void*)(g + (size_t)(m0+row)*1024 + koff + seg*8));
        }
    }
    #pragma unroll
    for (int t=0;t<2;t++){
        const __nv_bfloat16* g = t ? Blo : Bhi;
        #pragma unroll
        for (int i=0;i<BN/32;i++){            // BN rows x 8 segs
            int idx = tid + 256*i;
            int row = idx >> 3, seg = idx & 7;
            uint32_t sw = (uint32_t)((seg ^ (row & 7)) << 4);
            CP16(sbuf + 32768u + (uint32_t)t*SZB + (uint32_t)(row*128) + sw,
                 (const void*)(g + (size_t)(n0+row)*1024 + koff + seg*8));
        }
    }
    asm volatile("cp.async.commit_group;");
}

// EPI=0: Cout[(d*1024+m)*Wd + nc] = acc   (d = n0/Wd)
// EPI=1: GRU update: c=tanh(acc+bc); h = z*h+(1-z)*c  (Wd=1024, col = b*64+j)
template<int BN, int EPI>
__global__ __launch_bounds__(256,1)
void tc_gemm(const __nv_bfloat16* __restrict__ Ahi, const __nv_bfloat16* __restrict__ Alo,
             const __nv_bfloat16* __restrict__ Bhi, const __nv_bfloat16* __restrict__ Blo,
             float* __restrict__ Cout, int Wd,
             const float* __restrict__ bc0, const float* __restrict__ bc1,
             float* __restrict__ hbuf, const float* __restrict__ zbuf)
{
    constexpr int NT = BN/32;                 // 8-wide n-tiles per warp
    constexpr int NP = NT/2;                  // ldsm.x4 groups (16 rows each)
    constexpr uint32_t SZB = (uint32_t)BN*128u;
    constexpr uint32_t STG = 32768u + 2u*SZB; // stage size
    extern __shared__ __align__(128) char dyn_[];
    uint32_t sbase = smem_u32_(dyn_);
    const int tid = threadIdx.x, wid = tid>>5, lane = tid&31;
    const int mw = (wid>>2)*64, nw = (wid&3)*(BN/4);
    const int m0 = blockIdx.y*128, n0 = blockIdx.x*BN;

    float acc[4][NT][4];
    #pragma unroll
    for (int i=0;i<4;i++)
        #pragma unroll
        for (int j=0;j<NT;j++)
            #pragma unroll
            for (int q=0;q<4;q++) acc[i][j][q]=0.f;

    tc_load_stage4<BN>(0, sbase, Ahi,Alo,Bhi,Blo, m0,n0, tid);

    for (int c=0;c<16;c++){
        uint32_t buf = (uint32_t)(c & 1);
        if (c+1 < 16){
            tc_load_stage4<BN>(c+1, sbase + (buf^1u)*STG, Ahi,Alo,Bhi,Blo, m0,n0, tid);
            asm volatile("cp.async.wait_group 1;");
        } else {
            asm volatile("cp.async.wait_group 0;");
        }
        __syncthreads();

        uint32_t sA = sbase + buf*STG;
        #pragma unroll
        for (int ks=0; ks<4; ks++){
            uint32_t aH[4][4], aL[4][4], bH[NP][4], bL[NP][4];
            #pragma unroll
            for (int tm=0;tm<4;tm++){
                int row = mw + tm*16 + ((lane>>3)&1)*8 + (lane&7);
                int ksg = ks*2 + (lane>>4);
                uint32_t off = (uint32_t)(row*128) + (uint32_t)(((ksg ^ (row&7)))<<4);
                LDSM_X4(aH[tm][0],aH[tm][1],aH[tm][2],aH[tm][3], sA + off);
                LDSM_X4(aL[tm][0],aL[tm][1],aL[tm][2],aL[tm][3], sA + 16384u + off);
            }
            #pragma unroll
            for (int np=0;np<NP;np++){
                int row = nw + np*16 + ((lane>>4)&1)*8 + (lane&7);
                int ksg = ks*2 + ((lane>>3)&1);
                uint32_t off = (uint32_t)(row*128) + (uint32_t)(((ksg ^ (row&7)))<<4);
                LDSM_X4(bH[np][0],bH[np][1],bH[np][2],bH[np][3], sA + 32768u + off);
                LDSM_X4(bL[np][0],bL[np][1],bL[np][2],bL[np][3], sA + 32768u + SZB + off);
            }
            #pragma unroll
            for (int tm=0;tm<4;tm++)
            {
                #pragma unroll
                for (int tn=0;tn<NT;tn++){
                    int hi0 = (tn&1)?2:0, hi1 = (tn&1)?3:1, g = tn>>1;
                    MMA16816(acc[tm][tn][0],acc[tm][tn][1],acc[tm][tn][2],acc[tm][tn][3],
                             aH[tm][0],aH[tm][1],aH[tm][2],aH[tm][3], bH[g][hi0],bH[g][hi1]);
                    MMA16816(acc[tm][tn][0],acc[tm][tn][1],acc[tm][tn][2],acc[tm][tn][3],
                             aH[tm][0],aH[tm][1],aH[tm][2],aH[tm][3], bL[g][hi0],bL[g][hi1]);
                    MMA16816(acc[tm][tn][0],acc[tm][tn][1],acc[tm][tn][2],acc[tm][tn][3],
                             aL[tm][0],aL[tm][1],aL[tm][2],aL[tm][3], bH[g][hi0],bH[g][hi1]);
                }
            }
        }
        __syncthreads();
    }

    const int d = n0 / Wd;
    if (EPI == 0){
        #pragma unroll
        for (int tm=0;tm<4;tm++)
        {
            #pragma unroll
            for (int tn=0;tn<NT;tn++){
                int m = m0 + mw + tm*16 + (lane>>2);
                int nc = (n0 % Wd) + nw + tn*8 + (lane&3)*2;
                float* o0 = Cout + ((size_t)(d*1024 + m))*(size_t)Wd + nc;
                *reinterpret_cast<float2*>(o0) = make_float2(acc[tm][tn][0], acc[tm][tn][1]);
                float* o1 = o0 + (size_t)8*(size_t)Wd;
                *reinterpret_cast<float2*>(o1) = make_float2(acc[tm][tn][2], acc[tm][tn][3]);
            }
        }
    } else {
        const float* bc = d ? bc1 : bc0;
        #pragma unroll
        for (int tm=0;tm<4;tm++)
        {
            #pragma unroll
            for (int tn=0;tn<NT;tn++){
                int m = m0 + mw + tm*16 + (lane>>2);
                int nc = (n0 & 1023) + nw + tn*8 + (lane&3)*2;
                int b = nc>>6, j = nc&63;
                float bj0 = bc[j], bj1 = bc[j+1];
                size_t h0 = (((size_t)(d*1024 + m))*16 + b)*64 + j;
                {
                    float2 hv = *reinterpret_cast<float2*>(hbuf + h0);
                    float2 zv = *reinterpret_cast<const float2*>(zbuf + h0);
                    float c0 = tanhf(acc[tm][tn][0] + bj0);
                    float c1 = tanhf(acc[tm][tn][1] + bj1);
                    *reinterpret_cast<float2*>(hbuf + h0) =
                        make_float2(zv.x*hv.x + (1.f-zv.x)*c0, zv.y*hv.y + (1.f-zv.y)*c1);
                }
                {
                    size_t h1 = h0 + 8*16*64;
                    float2 hv = *reinterpret_cast<float2*>(hbuf + h1);
                    float2 zv = *reinterpret_cast<const float2*>(zbuf + h1);
                    float c0 = tanhf(acc[tm][tn][2] + bj0);
                    float c1 = tanhf(acc[tm][tn][3] + bj1);
                    *reinterpret_cast<float2*>(hbuf + h1) =
                        make_float2(zv.x*hv.x + (1.f-zv.x)*c0, zv.y*hv.y + (1.f-zv.y)*c1);
                }
            }
        }
    }
}

// ---- register-tiled fp32 SGEMM ----
template<int BN, bool RELU, bool BIAS>
__global__ __launch_bounds__(256)
void sgemm_k(const float* __restrict__ A, const float* __restrict__ Bm,
             float* __restrict__ C, int M, int N, int K,
             size_t sAz, size_t sBz, size_t sCz, const float* __restrict__ bias)
{
    constexpr int TN = BN/16;
    __shared__ float As[8][128];
    __shared__ float Bs[8][BN];
    const int tid=threadIdx.x, tx=tid&15, ty=tid>>4;
    const int m0=blockIdx.y*128, n0=blockIdx.x*BN;
    A += (size_t)blockIdx.z*sAz; Bm += (size_t)blockIdx.z*sBz; C += (size_t)blockIdx.z*sCz;

    float acc[8][TN];
    #pragma unroll
    for(int i=0;i<8;i++)
    {
        #pragma unroll
        for(int j=0;j<TN;j++) acc[i][j]=0.f;
    }

    const int arow=tid>>1, ak=(tid&1)*4, br=tid>>5;
    for(int kt=0; kt<K; kt+=8){
        float4 av = *reinterpret_cast<const float4*>(A + (size_t)(m0+arow)*K + kt + ak);
        As[ak+0][arow]=av.x; As[ak+1][arow]=av.y; As[ak+2][arow]=av.z; As[ak+3][arow]=av.w;
        if (BN==128){
            int bc=(tid&31)*4;
            float4 bv = *reinterpret_cast<const float4*>(Bm + (size_t)(kt+br)*N + n0 + bc);
            *reinterpret_cast<float4*>(&Bs[br][bc]) = bv;
        } else {
            int bc=(tid&31)*2;
            float2 bv = *reinterpret_cast<const float2*>(Bm + (size_t)(kt+br)*N + n0 + bc);
            *reinterpret_cast<float2*>(&Bs[br][bc]) = bv;
        }
        __syncthreads();
        #pragma unroll
        for(int k=0;k<8;k++){
            float4 a0 = *reinterpret_cast<const float4*>(&As[k][ty*8]);
            float4 a1 = *reinterpret_cast<const float4*>(&As[k][ty*8+4]);
            float av8[8]={a0.x,a0.y,a0.z,a0.w,a1.x,a1.y,a1.z,a1.w};
            float bv[TN];
            #pragma unroll
            for(int j=0;j<TN;j+=4){
                float4 b4 = *reinterpret_cast<const float4*>(&Bs[k][tx*TN+j]);
                bv[j]=b4.x; bv[j+1]=b4.y; bv[j+2]=b4.z; bv[j+3]=b4.w;
            }
            #pragma unroll
            for(int i=0;i<8;i++)
            {
                #pragma unroll
                for(int j=0;j<TN;j++) acc[i][j]=fmaf(av8[i],bv[j],acc[i][j]);
            }
        }
        __syncthreads();
    }
    #pragma unroll
    for(int i=0;i<8;i++){
        size_t cro = (size_t)(m0+ty*8+i)*N + n0 + tx*TN;
        #pragma unroll
        for(int j=0;j<TN;j+=4){
            float4 v = make_float4(acc[i][j],acc[i][j+1],acc[i][j+2],acc[i][j+3]);
            if (BIAS){ v.x+=bias[n0+tx*TN+j]; v.y+=bias[n0+tx*TN+j+1];
                       v.z+=bias[n0+tx*TN+j+2]; v.w+=bias[n0+tx*TN+j+3]; }
            if (RELU){ v.x=fmaxf(v.x,0.f); v.y=fmaxf(v.y,0.f); v.z=fmaxf(v.z,0.f); v.w=fmaxf(v.w,0.f); }
            *reinterpret_cast<float4*>(&C[cro+j]) = v;
        }
    }
}

// ---- fused zr GEMM: zr = agg@Wzr (+bias, sigmoid); writes g_z and g_xrh ----
__global__ __launch_bounds__(256)
void sgemm_zr(const float* __restrict__ A, const float* __restrict__ Bm,
              const float* __restrict__ x0, const float* __restrict__ x1,
              int nstr, int bstr, const float* __restrict__ hbuf,
              const float* __restrict__ bz0, const float* __restrict__ bz1,
              const float* __restrict__ br0, const float* __restrict__ br1)
{
    __shared__ float As[8][128];
    __shared__ float Bs[8][128];
    const int tid=threadIdx.x, tx=tid&15, ty=tid>>4;
    const int m0=blockIdx.y*128;
    const int d = blockIdx.z;
    A += (size_t)d<<21; Bm += (size_t)d*16384;

    float acc[8][8];
    #pragma unroll
    for(int i=0;i<8;i++)
    {
        #pragma unroll
        for(int j=0;j<8;j++) acc[i][j]=0.f;
    }

    const int arow=tid>>1, ak=(tid&1)*4, br=tid>>5;
    for(int kt=0; kt<128; kt+=8){
        float4 av = *reinterpret_cast<const float4*>(A + (size_t)(m0+arow)*128 + kt + ak);
        As[ak+0][arow]=av.x; As[ak+1][arow]=av.y; As[ak+2][arow]=av.z; As[ak+3][arow]=av.w;
        int bc=(tid&31)*4;
        float4 bv = *reinterpret_cast<const float4*>(Bm + (size_t)(kt+br)*128 + bc);
        *reinterpret_cast<float4*>(&Bs[br][bc]) = bv;
        __syncthreads();
        #pragma unroll
        for(int k=0;k<8;k++){
            float4 a0 = *reinterpret_cast<const float4*>(&As[k][ty*8]);
            float4 a1 = *reinterpret_cast<const float4*>(&As[k][ty*8+4]);
            float av8[8]={a0.x,a0.y,a0.z,a0.w,a1.x,a1.y,a1.z,a1.w};
            float bv8[8];
            #pragma unroll
            for(int j=0;j<8;j+=4){
                float4 b4 = *reinterpret_cast<const float4*>(&Bs[k][tx*8+j]);
                bv8[j]=b4.x; bv8[j+1]=b4.y; bv8[j+2]=b4.z; bv8[j+3]=b4.w;
            }
            #pragma unroll
            for(int i=0;i<8;i++)
            {
                #pragma unroll
                for(int j=0;j<8;j++) acc[i][j]=fmaf(av8[i],bv8[j],acc[i][j]);
            }
        }
        __syncthreads();
    }

    const float* xb  = d ? x1 : x0;
    const float* bzp = d ? bz1 : bz0;
    const float* brp = d ? br1 : br0;
    #pragma unroll
    for(int i=0;i<8;i++){
        int row = m0 + ty*8 + i;
        int n = row>>4, b = row&15;
        size_t rg = ((size_t)d<<14) + row;
        if (tx < 8){
            #pragma unroll
            for(int j=0;j<8;j+=4){
                int jj = tx*8+j;
                float4 bz4 = *reinterpret_cast<const float4*>(bzp + jj);
                float4 zv = make_float4(sig_(acc[i][j]+bz4.x),   sig_(acc[i][j+1]+bz4.y),
                                        sig_(acc[i][j+2]+bz4.z), sig_(acc[i][j+3]+bz4.w));
                *reinterpret_cast<float4*>(g_z + rg*64 + jj) = zv;
                float4 xv = *reinterpret_cast<const float4*>(xb + (size_t)n*nstr + (size_t)b*bstr + jj);
                *reinterpret_cast<float4*>(g_xrh + rg*128 + jj) = xv;
            }
        } else {
            #pragma unroll
            for(int j=0;j<8;j+=4){
                int jj = tx*8+j, j2 = jj-64;
                float4 br4 = *reinterpret_cast<const float4*>(brp + j2);
                float4 hv = *reinterpret_cast<const float4*>(hbuf + rg*64 + j2);
                float4 rv = make_float4(sig_(acc[i][j]+br4.x)*hv.x,   sig_(acc[i][j+1]+br4.y)*hv.y,
                                        sig_(acc[i][j+2]+br4.z)*hv.z, sig_(acc[i][j+3]+br4.w)*hv.w);
                *reinterpret_cast<float4*>(g_xrh + rg*128 + jj) = rv;
            }
        }
    }
}

// ---- v GEMM fused with transpose+split: v = xrh@Wc -> g_bt (transposed bf16 split) ----
__global__ __launch_bounds__(256)
void sgemm_v(const float* __restrict__ A, const float* __restrict__ Bm)
{
    __shared__ float As[8][128];
    __shared__ float Bs[8][64];
    __shared__ float vst[128][65];
    const int tid=threadIdx.x, tx=tid&15, ty=tid>>4;
    const int m0=blockIdx.y*128;
    const int d = blockIdx.z;
    A += (size_t)d<<21; Bm += (size_t)d*8192;

    float acc[8][4];
    #pragma unroll
    for(int i=0;i<8;i++)
    {
        #pragma unroll
        for(int j=0;j<4;j++) acc[i][j]=0.f;
    }

    const int arow=tid>>1, ak=(tid&1)*4, br=tid>>5;
    for(int kt=0; kt<128; kt+=8){
        float4 av = *reinterpret_cast<const float4*>(A + (size_t)(m0+arow)*128 + kt + ak);
        As[ak+0][arow]=av.x; As[ak+1][arow]=av.y; As[ak+2][arow]=av.z; As[ak+3][arow]=av.w;
        int bc=(tid&31)*2;
        float2 bv = *reinterpret_cast<const float2*>(Bm + (size_t)(kt+br)*64 + bc);
        *reinterpret_cast<float2*>(&Bs[br][bc]) = bv;
        __syncthreads();
        #pragma unroll
        for(int k=0;k<8;k++){
            float4 a0 = *reinterpret_cast<const float4*>(&As[k][ty*8]);
            float4 a1 = *reinterpret_cast<const float4*>(&As[k][ty*8+4]);
            float av8[8]={a0.x,a0.y,a0.z,a0.w,a1.x,a1.y,a1.z,a1.w};
            float4 b4 = *reinterpret_cast<const float4*>(&Bs[k][tx*4]);
            float bv4[4]={b4.x,b4.y,b4.z,b4.w};
            #pragma unroll
            for(int i=0;i<8;i++)
            {
                #pragma unroll
                for(int j=0;j<4;j++) acc[i][j]=fmaf(av8[i],bv4[j],acc[i][j]);
            }
        }
        __syncthreads();
    }

    // stage v into smem, then transposed split write
    #pragma unroll
    for(int i=0;i<8;i++)
    {
        #pragma unroll
        for(int j=0;j<4;j++) vst[ty*8+i][tx*4+j] = acc[i][j];
    }
    __syncthreads();

    const int n0l = m0 >> 4;     // 8 consecutive n's
    #pragma unroll
    for (int cc=0; cc<4; cc++){
        int c = tid*4 + cc;       // 0..1023
        int b = c>>6, j = c&63;
        __align__(16) __nv_bfloat16 hi8[8];
        __align__(16) __nv_bfloat16 lo8[8];
        #pragma unroll
        for (int k=0;k<8;k++){
            float v = vst[k*16+b][j];
            __nv_bfloat16 h = __float2bfloat16_rn(v);
            hi8[k]=h; lo8[k]=__float2bfloat16_rn(v - __bfloat162float(h));
        }
        size_t ob = ((size_t)(d*1024 + c))*1024 + n0l;
        *reinterpret_cast<uint4*>(&g_bt_hi[ob]) = *reinterpret_cast<uint4*>(hi8);
        *reinterpret_cast<uint4*>(&g_bt_lo[ob]) = *reinterpret_cast<uint4*>(lo8);
    }
}

// ---- host ----
extern "C" void kernel_launch(void* const* d_in, const int* in_sizes, int n_in,
                              void* d_out, int out_size)
{
    const float *inp =(const float*)d_in[0], *msk =(const float*)d_in[1];
    const float *adj =(const float*)d_in[2];
    const float *Wp1 =(const float*)d_in[3], *bp1=(const float*)d_in[4];
    const float *Wp2 =(const float*)d_in[5], *bp2=(const float*)d_in[6];
    const float *Wz_f=(const float*)d_in[7], *Wr_f=(const float*)d_in[8], *Wc_f=(const float*)d_in[9];
    const float *bz_f=(const float*)d_in[10],*br_f=(const float*)d_in[11],*bc_f=(const float*)d_in[12];
    const float *Wz_r=(const float*)d_in[13],*Wr_r=(const float*)d_in[14],*Wc_r=(const float*)d_in[15];
    const float *bz_r=(const float*)d_in[16],*br_r=(const float*)d_in[17],*bc_r=(const float*)d_in[18];
    const float *Wd1 =(const float*)d_in[19],*bd1=(const float*)d_in[20];
    const float *Wd2 =(const float*)d_in[21],*bd2=(const float*)d_in[22];
    float* outp = (float*)d_out;

    // dynamic smem: BN=256 -> 2*(32KB + 64KB) = 192KB ; BN=128 -> 128KB
    cudaFuncSetAttribute((const void*)tc_gemm<256,0>, cudaFuncAttributeMaxDynamicSharedMemorySize, 196608);
    cudaFuncSetAttribute((const void*)tc_gemm<128,1>, cudaFuncAttributeMaxDynamicSharedMemorySize, 131072);

    void* vp;
    #define GS(nm) cudaGetSymbolAddress(&vp,nm); float* p_##nm=(float*)vp;
    GS(g_p) GS(g_xp) GS(g_h) GS(g_agg) GS(g_xrh)
    GS(g_z) GS(g_wzr) GS(g_wc) GS(g_hcat) GS(g_s1)
    #undef GS
    cudaGetSymbolAddress(&vp, g_adj_hi); __nv_bfloat16* p_adj_hi=(__nv_bfloat16*)vp;
    cudaGetSymbolAddress(&vp, g_adj_lo); __nv_bfloat16* p_adj_lo=(__nv_bfloat16*)vp;
    cudaGetSymbolAddress(&vp, g_bt_hi);  __nv_bfloat16* p_bt_hi =(__nv_bfloat16*)vp;
    cudaGetSymbolAddress(&vp, g_bt_lo);  __nv_bfloat16* p_bt_lo =(__nv_bfloat16*)vp;

    seq_kernel  <<<ROWS/256,256>>>(inp, msk);
    pproj_kernel<<<ROWS,256>>>(Wp1, bp1);
    sgemm_k<64,false,true><<<dim3(1,ROWS/128,1),256>>>(p_g_p, Wp2, p_g_xp, ROWS,64,256, 0,0,0, bp2);
    zero_h_kernel<<<(L_*2*N_*B_*H_)/256,256>>>();
    pack_w_kernel<<<384,256>>>(Wz_f,Wr_f,Wc_f,Wz_r,Wr_r,Wc_r);
    adjsplit_kernel<<<4096,256>>>(adj);

    for (int t=0; t<T_; t++){
        for (int l=0; l<L_; l++){
            const float *x0,*x1; int nstr,bstr;
            if (l==0){ x0 = p_g_xp + (size_t)t*B_*N_*H_;
                       x1 = p_g_xp + (size_t)(T_-1-t)*B_*N_*H_;
                       nstr = H_; bstr = N_*H_; }
            else     { x0 = p_g_h; x1 = p_g_h + N_*B_*H_;
                       nstr = B_*H_; bstr = H_; }
            float* hbuf = p_g_h + (size_t)l*2*N_*B_*H_;

            btsplit_xh<<<dim3(64,32,2),256>>>(x0,x1,nstr,bstr,hbuf);
            tc_gemm<256,0><<<dim3(16,8),256,196608>>>(
                p_adj_hi,p_adj_lo,p_bt_hi,p_bt_lo, p_g_agg, 2048,
                nullptr,nullptr,nullptr,nullptr);
            sgemm_zr<<<dim3(1,128,2),256>>>(
                p_g_agg, p_g_wzr + l*32768,
                x0,x1,nstr,bstr, hbuf,
                bz_f+l*64, bz_r+l*64, br_f+l*64, br_r+l*64);
            sgemm_v<<<dim3(1,128,2),256>>>(p_g_xrh, p_g_wc + l*16384);
            tc_gemm<128,1><<<dim3(16,8),256,131072>>>(
                p_adj_hi,p_adj_lo,p_bt_hi,p_bt_lo, nullptr, 1024,
                bc_f+l*64, bc_r+l*64, hbuf, p_g_z);
        }
    }

    hcat_kernel<<<16384,256>>>();
    sgemm_k<128,true ,true><<<dim3(2,256,1),256>>>(p_g_hcat, Wd1, p_g_s1, 32768,256,128, 0,0,0, bd1);
    sgemm_k<64 ,false,true><<<dim3(1,256,1),256>>>(p_g_s1,  Wd2, outp,  32768,64,256,  0,0,0, bd2);
}

// round 11
// speedup vs baseline: 2.7456x; 1.0826x over previous
#include <cuda_runtime.h>
#include <cuda_bf16.h>
#include <cstdint>

#define T_ 12
#define B_ 16
#define N_ 1024
#define H_ 64
#define L_ 2
#define PROJ_ 256
#define ROWS (T_*B_*N_)
#define HALF (ROWS/2)

// ---- scratch (device globals; allocation-free) ----
__device__ __align__(16) float g_seq [ROWS*2];
__device__ __align__(16) float g_p   [(size_t)ROWS*PROJ_];
__device__ __align__(16) float g_xp  [(size_t)ROWS*H_];
__device__ __align__(16) float g_h   [L_*2*N_*B_*H_];     // [l][d][n][b][64]
__device__ __align__(16) float g_agg [2*N_*B_*128];       // [d][n*16+b][128]
__device__ __align__(16) float g_z   [2*N_*B_*64];
__device__ __align__(16) float g_hcat[(size_t)L_*B_*N_*128];
__device__ __align__(16) float g_s1  [(size_t)L_*B_*N_*PROJ_];
// bf16-split operands for tensor-core GEMM
__device__ __align__(256) __nv_bfloat16 g_adj_hi[1024*1024];
__device__ __align__(256) __nv_bfloat16 g_adj_lo[1024*1024];
__device__ __align__(256) __nv_bfloat16 g_bt_hi[(size_t)4096*1024];
__device__ __align__(256) __nv_bfloat16 g_bt_lo[(size_t)4096*1024];
// transposed split weights as uint32 bf16-pairs (k-pair packed, low k in low 16 bits)
__device__ __align__(256) uint32_t g_wzrT_hi[L_*2*128*64];
__device__ __align__(256) uint32_t g_wzrT_lo[L_*2*128*64];
__device__ __align__(256) uint32_t g_wcT_hi [L_*2*64*64];
__device__ __align__(256) uint32_t g_wcT_lo [L_*2*64*64];

// ---- threefry2x32-20, bit-exact JAX normal(key(42)) ----
__device__ __forceinline__ uint32_t rotl_(uint32_t x,int r){return (x<<r)|(x>>(32-r));}
__device__ float tf_noise(unsigned i)
{
    uint32_t x0,x1; bool second = (i >= (unsigned)HALF);
    if(second){x0=i-HALF; x1=i;} else {x0=i; x1=i+HALF;}
    const uint32_t ks0=0u, ks1=42u, ks2=0u^42u^0x1BD11BDAu;
    x0+=ks0; x1+=ks1;
#define TFR(r) {x0+=x1; x1=rotl_(x1,(r)); x1^=x0;}
    TFR(13)TFR(15)TFR(26)TFR(6)  x0+=ks1; x1+=ks2+1u;
    TFR(17)TFR(29)TFR(16)TFR(24) x0+=ks2; x1+=ks0+2u;
    TFR(13)TFR(15)TFR(26)TFR(6)  x0+=ks0; x1+=ks1+3u;
    TFR(17)TFR(29)TFR(16)TFR(24) x0+=ks1; x1+=ks2+4u;
    TFR(13)TFR(15)TFR(26)TFR(6)  x0+=ks2; x1+=ks0+5u;
#undef TFR
    uint32_t bits = second ? x1 : x0;
    float f = __uint_as_float((bits>>9)|0x3f800000u) - 1.0f;
    const float lo = -0.99999994f;
    float u = fmaxf(lo, fmaf(f, 2.0f, lo));
    return 1.41421356f * erfinvf(u) * 0.01f;
}

__device__ __forceinline__ float sig_(float x){ return 1.f/(1.f + expf(-x)); }

// pack two floats into bf16x2 hi, return hi, write lo residual pair
__device__ __forceinline__ uint32_t pack_split(float v0, float v1, uint32_t &lo)
{
    __nv_bfloat16 h0 = __float2bfloat16_rn(v0), h1 = __float2bfloat16_rn(v1);
    float r0 = v0 - __bfloat162float(h0), r1 = v1 - __bfloat162float(h1);
    __nv_bfloat16 l0 = __float2bfloat16_rn(r0), l1 = __float2bfloat16_rn(r1);
    lo = ((uint32_t)__bfloat16_as_ushort(l1)<<16) | (uint32_t)__bfloat16_as_ushort(l0);
    return ((uint32_t)__bfloat16_as_ushort(h1)<<16) | (uint32_t)__bfloat16_as_ushort(h0);
}

// ---- elementwise kernels ----
__global__ void seq_kernel(const float* __restrict__ in, const float* __restrict__ mk)
{
    unsigned i = blockIdx.x*256u + threadIdx.x;
    reinterpret_cast<float2*>(g_seq)[i] = make_float2(in[i] + tf_noise(i), mk[i]);
}

__global__ void pproj_kernel(const float* __restrict__ Wp1, const float* __restrict__ bp1)
{
    size_t gid = (size_t)blockIdx.x*256u + threadIdx.x;
    int j = (int)(gid & 255u); size_t row = gid >> 8;
    float2 s = reinterpret_cast<const float2*>(g_seq)[row];
    g_p[gid] = fmaxf(fmaf(s.x, Wp1[j], fmaf(s.y, Wp1[256+j], bp1[j])), 0.f);
}

__global__ void zero_h_kernel(){ g_h[blockIdx.x*256u + threadIdx.x] = 0.f; }

// FIXED bounds: wzr region is 32768 entries (2l*2d*128col*64kp), wc region 16384.
__global__ void pack_wT(const float* Wz_f,const float* Wr_f,const float* Wc_f,
                        const float* Wz_r,const float* Wr_r,const float* Wc_r)
{
    unsigned idx = blockIdx.x*256u + threadIdx.x;   // 192 blocks = 49152
    if (idx < 32768u){
        int kp = idx&63, col=(idx>>6)&127, d=(idx>>13)&1, l=idx>>14;
        const float* Wz = d?Wz_r:Wz_f; const float* Wr = d?Wr_r:Wr_f;
        int f0=2*kp, f1=2*kp+1;
        float v0 = (col<64)? Wz[(l*128+f0)*64+col] : Wr[(l*128+f0)*64+col-64];
        float v1 = (col<64)? Wz[(l*128+f1)*64+col] : Wr[(l*128+f1)*64+col-64];
        uint32_t lo; uint32_t hi = pack_split(v0,v1,lo);
        g_wzrT_hi[idx]=hi; g_wzrT_lo[idx]=lo;
    } else if (idx < 49152u){
        unsigned k = idx-32768u;
        int kp=k&63, c=(k>>6)&63, d=(k>>12)&1, l=k>>13;
        const float* Wc = d?Wc_r:Wc_f;
        float v0 = Wc[(l*128+2*kp)*64+c], v1 = Wc[(l*128+2*kp+1)*64+c];
        uint32_t lo; uint32_t hi = pack_split(v0,v1,lo);
        g_wcT_hi[k]=hi; g_wcT_lo[k]=lo;
    }
}

__global__ void hcat_kernel()
{
    unsigned idx = blockIdx.x*256u + threadIdx.x;
    int jj=idx&127, n=(idx>>7)&1023, b=(idx>>17)&15, l=idx>>21;
    int d=jj>>6, h=jj&63;
    g_hcat[idx] = g_h[((((size_t)l*2 + d)*N_ + n)*B_ + b)*H_ + h];
}

__global__ void adjsplit_kernel(const float* __restrict__ adj)
{
    unsigned i = blockIdx.x*256u + threadIdx.x;
    float a = adj[i];
    __nv_bfloat16 h = __float2bfloat16_rn(a);
    g_adj_hi[i] = h;
    g_adj_lo[i] = __float2bfloat16_rn(a - __bfloat162float(h));
}

// fused build_xh + transpose + split:
// bt[(d*2048 + c)*1024 + n] = xh(d,n,c) where c=b*128+f; f<64 -> x, f>=64 -> h
__global__ void btsplit_xh(const float* __restrict__ x0, const float* __restrict__ x1,
                           int nstr, int bstr, const float* __restrict__ hbuf)
{
    __shared__ float tile[32][33];
    int d = blockIdx.z;
    int c0 = blockIdx.x*32, n0 = blockIdx.y*32;
    int tx = threadIdx.x & 31, ty = threadIdx.x >> 5;
    int b = c0 >> 7, f0 = c0 & 127;
    const float* xb = d ? x1 : x0;
    #pragma unroll
    for (int i=0;i<4;i++){
        int n = n0 + ty + 8*i;
        int f = f0 + tx;
        float v;
        if (f < 64) v = xb[(size_t)n*nstr + (size_t)b*bstr + f];
        else        v = hbuf[(((size_t)d*1024 + n)*16 + b)*64 + (f-64)];
        tile[ty+8*i][tx] = v;
    }
    __syncthreads();
    size_t ob = ((size_t)(d*2048 + c0))*1024 + n0;
    #pragma unroll
    for (int i=0;i<4;i++){
        int c = ty + 8*i;
        float v = tile[tx][c];
        __nv_bfloat16 h = __float2bfloat16_rn(v);
        g_bt_hi[ob + (size_t)c*1024 + tx] = h;
        g_bt_lo[ob + (size_t)c*1024 + tx] = __float2bfloat16_rn(v - __bfloat162float(h));
    }
}

// ---- tensor-core split-bf16 GEMM (adjacency) ----
__device__ __forceinline__ uint32_t smem_u32_(const void* p){
    uint32_t a;
    asm("{ .reg .u64 t; cvta.to.shared.u64 t, %1; cvt.u32.u64 %0, t; }":"=r"(a):"l"(p));
    return a;
}
#define LDSM_X4(r0,r1,r2,r3,addr) \
    asm volatile("ldmatrix.sync.aligned.m8n8.x4.shared.b16 {%0,%1,%2,%3}, [%4];" \
        : "=r"(r0),"=r"(r1),"=r"(r2),"=r"(r3) : "r"(addr))
#define MMA16816(d0,d1,d2,d3,a0,a1,a2,a3,b0,b1) \
    asm volatile("mma.sync.aligned.m16n8k16.row.col.f32.bf16.bf16.f32 " \
        "{%0,%1,%2,%3}, {%4,%5,%6,%7}, {%8,%9}, {%0,%1,%2,%3};" \
        : "+f"(d0),"+f"(d1),"+f"(d2),"+f"(d3) \
        : "r"(a0),"r"(a1),"r"(a2),"r"(a3),"r"(b0),"r"(b1))
#define CP16(dst,src) asm volatile("cp.async.cg.shared.global [%0], [%1], 16;"::"r"(dst),"l"(src))

template<int BN>
__device__ __forceinline__ void tc_load_stage4(
    int kc, uint32_t sbuf,
    const __nv_bfloat16* __restrict__ Ahi, const __nv_bfloat16* __restrict__ Alo,
    const __nv_bfloat16* __restrict__ Bhi, const __nv_bfloat16* __restrict__ Blo,
    int m0, int n0, int tid)
{
    constexpr uint32_t SZB = (uint32_t)BN*128u;
    int koff = kc*64;
    #pragma unroll
    for (int t=0;t<2;t++){
        const __nv_bfloat16* g = t ? Alo : Ahi;
        #pragma unroll
        for (int i=0;i<4;i++){
            int idx = tid + 256*i;
            int row = idx >> 3, seg = idx & 7;
            uint32_t sw = (uint32_t)((seg ^ (row & 7)) << 4);
            CP16(sbuf + (uint32_t)t*16384u + (uint32_t)(row*128) + sw,
                 (const void*)(g + (size_t)(m0+row)*1024 + koff + seg*8));
        }
    }
    #pragma unroll
    for (int t=0;t<2;t++){
        const __nv_bfloat16* g = t ? Blo : Bhi;
        #pragma unroll
        for (int i=0;i<BN/32;i++){
            int idx = tid + 256*i;
            int row = idx >> 3, seg = idx & 7;
            uint32_t sw = (uint32_t)((seg ^ (row & 7)) << 4);
            CP16(sbuf + 32768u + (uint32_t)t*SZB + (uint32_t)(row*128) + sw,
                 (const void*)(g + (size_t)(n0+row)*1024 + koff + seg*8));
        }
    }
    asm volatile("cp.async.commit_group;");
}

// EPI=0: Cout[(d*1024+m)*Wd + nc] = acc   (d = n0/Wd)
// EPI=1: GRU update: c=tanh(acc+bc); h = z*h+(1-z)*c  (Wd=1024, col = b*64+j)
template<int BN, int EPI>
__global__ __launch_bounds__(256,1)
void tc_gemm(const __nv_bfloat16* __restrict__ Ahi, const __nv_bfloat16* __restrict__ Alo,
             const __nv_bfloat16* __restrict__ Bhi, const __nv_bfloat16* __restrict__ Blo,
             float* __restrict__ Cout, int Wd,
             const float* __restrict__ bc0, const float* __restrict__ bc1,
             float* __restrict__ hbuf, const float* __restrict__ zbuf)
{
    constexpr int NT = BN/32;
    constexpr int NP = NT/2;
    constexpr uint32_t SZB = (uint32_t)BN*128u;
    constexpr uint32_t STG = 32768u + 2u*SZB;
    extern __shared__ __align__(128) char dyn_[];
    uint32_t sbase = smem_u32_(dyn_);
    const int tid = threadIdx.x, wid = tid>>5, lane = tid&31;
    const int mw = (wid>>2)*64, nw = (wid&3)*(BN/4);
    const int m0 = blockIdx.y*128, n0 = blockIdx.x*BN;

    float acc[4][NT][4];
    #pragma unroll
    for (int i=0;i<4;i++)
        #pragma unroll
        for (int j=0;j<NT;j++)
            #pragma unroll
            for (int q=0;q<4;q++) acc[i][j][q]=0.f;

    tc_load_stage4<BN>(0, sbase, Ahi,Alo,Bhi,Blo, m0,n0, tid);

    for (int c=0;c<16;c++){
        uint32_t buf = (uint32_t)(c & 1);
        if (c+1 < 16){
            tc_load_stage4<BN>(c+1, sbase + (buf^1u)*STG, Ahi,Alo,Bhi,Blo, m0,n0, tid);
            asm volatile("cp.async.wait_group 1;");
        } else {
            asm volatile("cp.async.wait_group 0;");
        }
        __syncthreads();

        uint32_t sA = sbase + buf*STG;
        #pragma unroll
        for (int ks=0; ks<4; ks++){
            uint32_t aH[4][4], aL[4][4], bH[NP][4], bL[NP][4];
            #pragma unroll
            for (int tm=0;tm<4;tm++){
                int row = mw + tm*16 + ((lane>>3)&1)*8 + (lane&7);
                int ksg = ks*2 + (lane>>4);
                uint32_t off = (uint32_t)(row*128) + (uint32_t)(((ksg ^ (row&7)))<<4);
                LDSM_X4(aH[tm][0],aH[tm][1],aH[tm][2],aH[tm][3], sA + off);
                LDSM_X4(aL[tm][0],aL[tm][1],aL[tm][2],aL[tm][3], sA + 16384u + off);
            }
            #pragma unroll
            for (int np=0;np<NP;np++){
                int row = nw + np*16 + ((lane>>4)&1)*8 + (lane&7);
                int ksg = ks*2 + ((lane>>3)&1);
                uint32_t off = (uint32_t)(row*128) + (uint32_t)(((ksg ^ (row&7)))<<4);
                LDSM_X4(bH[np][0],bH[np][1],bH[np][2],bH[np][3], sA + 32768u + off);
                LDSM_X4(bL[np][0],bL[np][1],bL[np][2],bL[np][3], sA + 32768u + SZB + off);
            }
            #pragma unroll
            for (int tm=0;tm<4;tm++)
            {
                #pragma unroll
                for (int tn=0;tn<NT;tn++){
                    int hi0 = (tn&1)?2:0, hi1 = (tn&1)?3:1, g = tn>>1;
                    MMA16816(acc[tm][tn][0],acc[tm][tn][1],acc[tm][tn][2],acc[tm][tn][3],
                             aH[tm][0],aH[tm][1],aH[tm][2],aH[tm][3], bH[g][hi0],bH[g][hi1]);
                    MMA16816(acc[tm][tn][0],acc[tm][tn][1],acc[tm][tn][2],acc[tm][tn][3],
                             aH[tm][0],aH[tm][1],aH[tm][2],aH[tm][3], bL[g][hi0],bL[g][hi1]);
                    MMA16816(acc[tm][tn][0],acc[tm][tn][1],acc[tm][tn][2],acc[tm][tn][3],
                             aL[tm][0],aL[tm][1],aL[tm][2],aL[tm][3], bH[g][hi0],bH[g][hi1]);
                }
            }
        }
        __syncthreads();
    }

    const int d = n0 / Wd;
    if (EPI == 0){
        #pragma unroll
        for (int tm=0;tm<4;tm++)
        {
            #pragma unroll
            for (int tn=0;tn<NT;tn++){
                int m = m0 + mw + tm*16 + (lane>>2);
                int nc = (n0 % Wd) + nw + tn*8 + (lane&3)*2;
                float* o0 = Cout + ((size_t)(d*1024 + m))*(size_t)Wd + nc;
                *reinterpret_cast<float2*>(o0) = make_float2(acc[tm][tn][0], acc[tm][tn][1]);
                float* o1 = o0 + (size_t)8*(size_t)Wd;
                *reinterpret_cast<float2*>(o1) = make_float2(acc[tm][tn][2], acc[tm][tn][3]);
            }
        }
    } else {
        const float* bc = d ? bc1 : bc0;
        #pragma unroll
        for (int tm=0;tm<4;tm++)
        {
            #pragma unroll
            for (int tn=0;tn<NT;tn++){
                int m = m0 + mw + tm*16 + (lane>>2);
                int nc = (n0 & 1023) + nw + tn*8 + (lane&3)*2;
                int b = nc>>6, j = nc&63;
                float bj0 = bc[j], bj1 = bc[j+1];
                size_t h0 = (((size_t)(d*1024 + m))*16 + b)*64 + j;
                {
                    float2 hv = *reinterpret_cast<float2*>(hbuf + h0);
                    float2 zv = *reinterpret_cast<const float2*>(zbuf + h0);
                    float c0 = tanhf(acc[tm][tn][0] + bj0);
                    float c1 = tanhf(acc[tm][tn][1] + bj1);
                    *reinterpret_cast<float2*>(hbuf + h0) =
                        make_float2(zv.x*hv.x + (1.f-zv.x)*c0, zv.y*hv.y + (1.f-zv.y)*c1);
                }
                {
                    size_t h1 = h0 + 8*16*64;
                    float2 hv = *reinterpret_cast<float2*>(hbuf + h1);
                    float2 zv = *reinterpret_cast<const float2*>(zbuf + h1);
                    float c0 = tanhf(acc[tm][tn][2] + bj0);
                    float c1 = tanhf(acc[tm][tn][3] + bj1);
                    *reinterpret_cast<float2*>(hbuf + h1) =
                        make_float2(zv.x*hv.x + (1.f-zv.x)*c0, zv.y*hv.y + (1.f-zv.y)*c1);
                }
            }
        }
    }
}

// ---- fused tensor-core zr + v kernel ----
// grid (128, 2): CTA = 128 rows of one dir. Computes zr = agg@Wzr (sigmoid, bias),
// writes g_z, builds xrh fragments in-register, v = xrh@Wc, writes transposed
// bf16-split v into g_bt.
#define ZRV_SMEM (2*128*68*4 + 2*64*68*4 + 2*1024*8*2)
__global__ __launch_bounds__(256,1)
void zrv_tc(const float* __restrict__ agg,
            const uint32_t* __restrict__ wzh, const uint32_t* __restrict__ wzl,
            const uint32_t* __restrict__ wch, const uint32_t* __restrict__ wcl,
            const float* __restrict__ x0, const float* __restrict__ x1,
            int nstr, int bstr, const float* __restrict__ hbuf,
            const float* __restrict__ bz0, const float* __restrict__ bz1,
            const float* __restrict__ br0, const float* __restrict__ br1)
{
    extern __shared__ __align__(16) char dyn_[];
    uint32_t* sWzh = (uint32_t*)dyn_;             // [128][68]
    uint32_t* sWzl = sWzh + 128*68;
    uint32_t* sWch = sWzl + 128*68;               // [64][68]
    uint32_t* sWcl = sWch + 64*68;
    __nv_bfloat16* vsh = (__nv_bfloat16*)(sWcl + 64*68);   // [1024][8]
    __nv_bfloat16* vsl = vsh + 1024*8;

    const int tid = threadIdx.x, wid = tid>>5, lane = tid&31;
    const int d = blockIdx.y;
    const int qk = lane & 3;
    const int r0 = blockIdx.x*128 + wid*16 + (lane>>2);   // row within dir (r0 and r0+8)

    wzh += (size_t)d*8192; wzl += (size_t)d*8192;
    wch += (size_t)d*4096; wcl += (size_t)d*4096;
    for (int i=tid;i<8192;i+=256){ int n=i>>6, kp=i&63; sWzh[n*68+kp]=wzh[i]; sWzl[n*68+kp]=wzl[i]; }
    for (int i=tid;i<4096;i+=256){ int n=i>>6, kp=i&63; sWch[n*68+kp]=wch[i]; sWcl[n*68+kp]=wcl[i]; }
    __syncthreads();

    // ---- zr MMA: acc[16 n-tiles][4], K=128 ----
    float acc[16][4];
    #pragma unroll
    for (int t=0;t<16;t++)
    {
        #pragma unroll
        for (int q=0;q<4;q++) acc[t][q]=0.f;
    }
    const float* aggd = agg + ((size_t)d<<14)*128;
    #pragma unroll
    for (int kt=0;kt<8;kt++){
        float2 a00 = *(const float2*)(aggd + (size_t)r0*128     + kt*16     + 2*qk);
        float2 a10 = *(const float2*)(aggd + (size_t)(r0+8)*128 + kt*16     + 2*qk);
        float2 a01 = *(const float2*)(aggd + (size_t)r0*128     + kt*16 + 8 + 2*qk);
        float2 a11 = *(const float2*)(aggd + (size_t)(r0+8)*128 + kt*16 + 8 + 2*qk);
        uint32_t ah[4], al[4];
        ah[0]=pack_split(a00.x,a00.y,al[0]); ah[1]=pack_split(a10.x,a10.y,al[1]);
        ah[2]=pack_split(a01.x,a01.y,al[2]); ah[3]=pack_split(a11.x,a11.y,al[3]);
        #pragma unroll
        for (int tn=0;tn<16;tn++){
            int nb = (tn*8 + (lane>>2))*68 + kt*8;
            uint32_t bh0=sWzh[nb+qk], bh1=sWzh[nb+4+qk];
            uint32_t bl0=sWzl[nb+qk], bl1=sWzl[nb+4+qk];
            MMA16816(acc[tn][0],acc[tn][1],acc[tn][2],acc[tn][3], ah[0],ah[1],ah[2],ah[3], bh0,bh1);
            MMA16816(acc[tn][0],acc[tn][1],acc[tn][2],acc[tn][3], ah[0],ah[1],ah[2],ah[3], bl0,bl1);
            MMA16816(acc[tn][0],acc[tn][1],acc[tn][2],acc[tn][3], al[0],al[1],al[2],al[3], bh0,bh1);
        }
    }

    // ---- epilogue: z (tiles 0-7), rh (tiles 8-15) ----
    const float* bzp = d?bz1:bz0;
    const float* brp = d?br1:br0;
    float* zout = g_z + ((size_t)d<<14)*64;
    #pragma unroll
    for (int tn=0;tn<8;tn++){
        int col = tn*8 + 2*qk;
        float2 bz2 = *(const float2*)(bzp + col);
        *(float2*)(zout + (size_t)r0*64 + col) =
            make_float2(sig_(acc[tn][0]+bz2.x), sig_(acc[tn][1]+bz2.y));
        *(float2*)(zout + (size_t)(r0+8)*64 + col) =
            make_float2(sig_(acc[tn][2]+bz2.x), sig_(acc[tn][3]+bz2.y));
    }
    uint32_t rhh[4][4], rhl[4][4];
    const float* hd = hbuf + ((size_t)d<<14)*64;
    #pragma unroll
    for (int j=0;j<4;j++)
    {
        #pragma unroll
        for (int s=0;s<2;s++){
            int tn = 8 + 2*j + s;
            int j2 = tn*8 - 64 + 2*qk;
            float2 br2 = *(const float2*)(brp + j2);
            float2 h0 = *(const float2*)(hd + (size_t)r0*64 + j2);
            float2 h1 = *(const float2*)(hd + (size_t)(r0+8)*64 + j2);
            float v00 = sig_(acc[tn][0]+br2.x)*h0.x, v01 = sig_(acc[tn][1]+br2.y)*h0.y;
            float v10 = sig_(acc[tn][2]+br2.x)*h1.x, v11 = sig_(acc[tn][3]+br2.y)*h1.y;
            rhh[j][0+2*s] = pack_split(v00,v01, rhl[j][0+2*s]);
            rhh[j][1+2*s] = pack_split(v10,v11, rhl[j][1+2*s]);
        }
    }

    // ---- v MMA: accv[8][4], K=128 (x: kt 0-3 from global, rh: kt 4-7 from regs) ----
    float accv[8][4];
    #pragma unroll
    for (int t=0;t<8;t++)
    {
        #pragma unroll
        for (int q=0;q<4;q++) accv[t][q]=0.f;
    }
    const float* xb = d ? x1 : x0;
    const size_t xbase = (size_t)(r0>>4)*nstr;
    const int b0i = r0 & 15;
    #pragma unroll
    for (int j=0;j<4;j++){
        int f = 16*j + 2*qk;
        float2 x00 = *(const float2*)(xb + xbase + (size_t)b0i*bstr + f);
        float2 x10 = *(const float2*)(xb + xbase + (size_t)(b0i+8)*bstr + f);
        float2 x01 = *(const float2*)(xb + xbase + (size_t)b0i*bstr + f+8);
        float2 x11 = *(const float2*)(xb + xbase + (size_t)(b0i+8)*bstr + f+8);
        uint32_t ah[4], al[4];
        ah[0]=pack_split(x00.x,x00.y,al[0]); ah[1]=pack_split(x10.x,x10.y,al[1]);
        ah[2]=pack_split(x01.x,x01.y,al[2]); ah[3]=pack_split(x11.x,x11.y,al[3]);
        #pragma unroll
        for (int vt=0;vt<8;vt++){
            int nb = (vt*8 + (lane>>2))*68 + j*8;
            uint32_t bh0=sWch[nb+qk], bh1=sWch[nb+4+qk];
            uint32_t bl0=sWcl[nb+qk], bl1=sWcl[nb+4+qk];
            MMA16816(accv[vt][0],accv[vt][1],accv[vt][2],accv[vt][3], ah[0],ah[1],ah[2],ah[3], bh0,bh1);
            MMA16816(accv[vt][0],accv[vt][1],accv[vt][2],accv[vt][3], ah[0],ah[1],ah[2],ah[3], bl0,bl1);
            MMA16816(accv[vt][0],accv[vt][1],accv[vt][2],accv[vt][3], al[0],al[1],al[2],al[3], bh0,bh1);
        }
    }
    #pragma unroll
    for (int j=0;j<4;j++)
    {
        #pragma unroll
        for (int vt=0;vt<8;vt++){
            int nb = (vt*8 + (lane>>2))*68 + (4+j)*8;
            uint32_t bh0=sWch[nb+qk], bh1=sWch[nb+4+qk];
            uint32_t bl0=sWcl[nb+qk], bl1=sWcl[nb+4+qk];
            MMA16816(accv[vt][0],accv[vt][1],accv[vt][2],accv[vt][3],
                     rhh[j][0],rhh[j][1],rhh[j][2],rhh[j][3], bh0,bh1);
            MMA16816(accv[vt][0],accv[vt][1],accv[vt][2],accv[vt][3],
                     rhh[j][0],rhh[j][1],rhh[j][2],rhh[j][3], bl0,bl1);
            MMA16816(accv[vt][0],accv[vt][1],accv[vt][2],accv[vt][3],
                     rhl[j][0],rhl[j][1],rhl[j][2],rhl[j][3], bh0,bh1);
        }
    }

    // ---- v epilogue: stage transposed bf16 split, coalesced write ----
    const int nl = (r0>>4) & 7;
    #pragma unroll
    for (int vt=0;vt<8;vt++){
        int c = vt*8 + 2*qk;
        int vc0 = b0i*64 + c;
        int vc1 = (b0i+8)*64 + c;
        float v00=accv[vt][0], v01=accv[vt][1], v10=accv[vt][2], v11=accv[vt][3];
        __nv_bfloat16 h;
        h=__float2bfloat16_rn(v00); vsh[(size_t)vc0*8+nl]=h;     vsl[(size_t)vc0*8+nl]=__float2bfloat16_rn(v00-__bfloat162float(h));
        h=__float2bfloat16_rn(v01); vsh[(size_t)(vc0+1)*8+nl]=h; vsl[(size_t)(vc0+1)*8+nl]=__float2bfloat16_rn(v01-__bfloat162float(h));
        h=__float2bfloat16_rn(v10); vsh[(size_t)vc1*8+nl]=h;     vsl[(size_t)vc1*8+nl]=__float2bfloat16_rn(v10-__bfloat162float(h));
        h=__float2bfloat16_rn(v11); vsh[(size_t)(vc1+1)*8+nl]=h; vsl[(size_t)(vc1+1)*8+nl]=__float2bfloat16_rn(v11-__bfloat162float(h));
    }
    __syncthreads();
    const int nb0 = blockIdx.x*8;
    #pragma unroll
    for (int i=0;i<4;i++){
        int vc = tid + 256*i;
        *(uint4*)(&g_bt_hi[((size_t)(d*1024) + vc)*1024 + nb0]) = *(uint4*)(&vsh[(size_t)vc*8]);
        *(uint4*)(&g_bt_lo[((size_t)(d*1024) + vc)*1024 + nb0]) = *(uint4*)(&vsl[(size_t)vc*8]);
    }
}

// ---- register-tiled fp32 SGEMM (pre/post processing) ----
template<int BN, bool RELU, bool BIAS>
__global__ __launch_bounds__(256)
void sgemm_k(const float* __restrict__ A, const float* __restrict__ Bm,
             float* __restrict__ C, int M, int N, int K,
             size_t sAz, size_t sBz, size_t sCz, const float* __restrict__ bias)
{
    constexpr int TN = BN/16;
    __shared__ float As[8][128];
    __shared__ float Bs[8][BN];
    const int tid=threadIdx.x, tx=tid&15, ty=tid>>4;
    const int m0=blockIdx.y*128, n0=blockIdx.x*BN;
    A += (size_t)blockIdx.z*sAz; Bm += (size_t)blockIdx.z*sBz; C += (size_t)blockIdx.z*sCz;

    float acc[8][TN];
    #pragma unroll
    for(int i=0;i<8;i++)
    {
        #pragma unroll
        for(int j=0;j<TN;j++) acc[i][j]=0.f;
    }

    const int arow=tid>>1, ak=(tid&1)*4, br=tid>>5;
    for(int kt=0; kt<K; kt+=8){
        float4 av = *reinterpret_cast<const float4*>(A + (size_t)(m0+arow)*K + kt + ak);
        As[ak+0][arow]=av.x; As[ak+1][arow]=av.y; As[ak+2][arow]=av.z; As[ak+3][arow]=av.w;
        if (BN==128){
            int bc=(tid&31)*4;
            float4 bv = *reinterpret_cast<const float4*>(Bm + (size_t)(kt+br)*N + n0 + bc);
            *reinterpret_cast<float4*>(&Bs[br][bc]) = bv;
        } else {
            int bc=(tid&31)*2;
            float2 bv = *reinterpret_cast<const float2*>(Bm + (size_t)(kt+br)*N + n0 + bc);
            *reinterpret_cast<float2*>(&Bs[br][bc]) = bv;
        }
        __syncthreads();
        #pragma unroll
        for(int k=0;k<8;k++){
            float4 a0 = *reinterpret_cast<const float4*>(&As[k][ty*8]);
            float4 a1 = *reinterpret_cast<const float4*>(&As[k][ty*8+4]);
            float av8[8]={a0.x,a0.y,a0.z,a0.w,a1.x,a1.y,a1.z,a1.w};
            float bv[TN];
            #pragma unroll
            for(int j=0;j<TN;j+=4){
                float4 b4 = *reinterpret_cast<const float4*>(&Bs[k][tx*TN+j]);
                bv[j]=b4.x; bv[j+1]=b4.y; bv[j+2]=b4.z; bv[j+3]=b4.w;
            }
            #pragma unroll
            for(int i=0;i<8;i++)
            {
                #pragma unroll
                for(int j=0;j<TN;j++) acc[i][j]=fmaf(av8[i],bv[j],acc[i][j]);
            }
        }
        __syncthreads();
    }
    #pragma unroll
    for(int i=0;i<8;i++){
        size_t cro = (size_t)(m0+ty*8+i)*N + n0 + tx*TN;
        #pragma unroll
        for(int j=0;j<TN;j+=4){
            float4 v = make_float4(acc[i][j],acc[i][j+1],acc[i][j+2],acc[i][j+3]);
            if (BIAS){ v.x+=bias[n0+tx*TN+j]; v.y+=bias[n0+tx*TN+j+1];
                       v.z+=bias[n0+tx*TN+j+2]; v.w+=bias[n0+tx*TN+j+3]; }
            if (RELU){ v.x=fmaxf(v.x,0.f); v.y=fmaxf(v.y,0.f); v.z=fmaxf(v.z,0.f); v.w=fmaxf(v.w,0.f); }
            *reinterpret_cast<float4*>(&C[cro+j]) = v;
        }
    }
}

// ---- host ----
extern "C" void kernel_launch(void* const* d_in, const int* in_sizes, int n_in,
                              void* d_out, int out_size)
{
    const float *inp =(const float*)d_in[0], *msk =(const float*)d_in[1];
    const float *adj =(const float*)d_in[2];
    const float *Wp1 =(const float*)d_in[3], *bp1=(const float*)d_in[4];
    const float *Wp2 =(const float*)d_in[5], *bp2=(const float*)d_in[6];
    const float *Wz_f=(const float*)d_in[7], *Wr_f=(const float*)d_in[8], *Wc_f=(const float*)d_in[9];
    const float *bz_f=(const float*)d_in[10],*br_f=(const float*)d_in[11],*bc_f=(const float*)d_in[12];
    const float *Wz_r=(const float*)d_in[13],*Wr_r=(const float*)d_in[14],*Wc_r=(const float*)d_in[15];
    const float *bz_r=(const float*)d_in[16],*br_r=(const float*)d_in[17],*bc_r=(const float*)d_in[18];
    const float *Wd1 =(const float*)d_in[19],*bd1=(const float*)d_in[20];
    const float *Wd2 =(const float*)d_in[21],*bd2=(const float*)d_in[22];
    float* outp = (float*)d_out;

    cudaFuncSetAttribute((const void*)tc_gemm<256,0>, cudaFuncAttributeMaxDynamicSharedMemorySize, 196608);
    cudaFuncSetAttribute((const void*)tc_gemm<128,1>, cudaFuncAttributeMaxDynamicSharedMemorySize, 131072);
    cudaFuncSetAttribute((const void*)zrv_tc,         cudaFuncAttributeMaxDynamicSharedMemorySize, ZRV_SMEM);

    void* vp;
    #define GS(nm) cudaGetSymbolAddress(&vp,nm); float* p_##nm=(float*)vp;
    GS(g_p) GS(g_xp) GS(g_h) GS(g_agg) GS(g_z) GS(g_hcat) GS(g_s1)
    #undef GS
    cudaGetSymbolAddress(&vp, g_adj_hi); __nv_bfloat16* p_adj_hi=(__nv_bfloat16*)vp;
    cudaGetSymbolAddress(&vp, g_adj_lo); __nv_bfloat16* p_adj_lo=(__nv_bfloat16*)vp;
    cudaGetSymbolAddress(&vp, g_bt_hi);  __nv_bfloat16* p_bt_hi =(__nv_bfloat16*)vp;
    cudaGetSymbolAddress(&vp, g_bt_lo);  __nv_bfloat16* p_bt_lo =(__nv_bfloat16*)vp;
    cudaGetSymbolAddress(&vp, g_wzrT_hi); uint32_t* p_wzh=(uint32_t*)vp;
    cudaGetSymbolAddress(&vp, g_wzrT_lo); uint32_t* p_wzl=(uint32_t*)vp;
    cudaGetSymbolAddress(&vp, g_wcT_hi);  uint32_t* p_wch=(uint32_t*)vp;
    cudaGetSymbolAddress(&vp, g_wcT_lo);  uint32_t* p_wcl=(uint32_t*)vp;

    seq_kernel  <<<ROWS/256,256>>>(inp, msk);
    pproj_kernel<<<ROWS,256>>>(Wp1, bp1);
    sgemm_k<64,false,true><<<dim3(1,ROWS/128,1),256>>>(p_g_p, Wp2, p_g_xp, ROWS,64,256, 0,0,0, bp2);
    zero_h_kernel<<<(L_*2*N_*B_*H_)/256,256>>>();
    pack_wT<<<192,256>>>(Wz_f,Wr_f,Wc_f,Wz_r,Wr_r,Wc_r);
    adjsplit_kernel<<<4096,256>>>(adj);

    for (int t=0; t<T_; t++){
        for (int l=0; l<L_; l++){
            const float *x0,*x1; int nstr,bstr;
            if (l==0){ x0 = p_g_xp + (size_t)t*B_*N_*H_;
                       x1 = p_g_xp + (size_t)(T_-1-t)*B_*N_*H_;
                       nstr = H_; bstr = N_*H_; }
            else     { x0 = p_g_h; x1 = p_g_h + N_*B_*H_;
                       nstr = B_*H_; bstr = H_; }
            float* hbuf = p_g_h + (size_t)l*2*N_*B_*H_;

            btsplit_xh<<<dim3(64,32,2),256>>>(x0,x1,nstr,bstr,hbuf);
            tc_gemm<256,0><<<dim3(16,8),256,196608>>>(
                p_adj_hi,p_adj_lo,p_bt_hi,p_bt_lo, p_g_agg, 2048,
                nullptr,nullptr,nullptr,nullptr);
            zrv_tc<<<dim3(128,2),256,ZRV_SMEM>>>(
                p_g_agg,
                p_wzh + l*16384, p_wzl + l*16384,
                p_wch + l*8192,  p_wcl + l*8192,
                x0,x1,nstr,bstr, hbuf,
                bz_f+l*64, bz_r+l*64, br_f+l*64, br_r+l*64);
            tc_gemm<128,1><<<dim3(16,8),256,131072>>>(
                p_adj_hi,p_adj_lo,p_bt_hi,p_bt_lo, nullptr, 1024,
                bc_f+l*64, bc_r+l*64, hbuf, p_g_z);
        }
    }

    hcat_kernel<<<16384,256>>>();
    sgemm_k<128,true ,true><<<dim3(2,256,1),256>>>(p_g_hcat, Wd1, p_g_s1, 32768,256,128, 0,0,0, bd1);
    sgemm_k<64 ,false,true><<<dim3(1,256,1),256>>>(p_g_s1,  Wd2, outp,  32768,64,256,  0,0,0, bd2);
}